// round 2
// baseline (speedup 1.0000x reference)
#include <cuda_runtime.h>
#include <stdint.h>

#define K_DIM 4096
#define N_DIM 16384
#define M_MAX 8192

#define BM 128
#define BN 256
#define BK 128                      // bytes of K per stage (int8)
#define STAGES 3
#define KSTEPS (K_DIM / BK)         // 32
#define A_SMEM (BM * BK)            // 16384
#define B_SMEM (BN * BK)            // 32768
#define STAGE_BYTES (A_SMEM + B_SMEM)   // 49152
#define GEMM_SMEM (STAGES * STAGE_BYTES) // 147456

// ------------------------- scratch (device globals; no runtime alloc) ---
__device__ char g_xq[(size_t)M_MAX * K_DIM];    // 32 MB int8 x
__device__ char g_wq[(size_t)N_DIM * K_DIM];    // 64 MB int8 w
__device__ float g_sx[M_MAX];

// ------------------------- helpers --------------------------------------
__device__ __forceinline__ uint32_t smem_u32(const void* p) {
    uint32_t a;
    asm("{ .reg .u64 t; cvta.to.shared.u64 t, %1; cvt.u32.u64 %0, t; }"
        : "=r"(a) : "l"(p));
    return a;
}
__device__ __forceinline__ uint32_t swz128(uint32_t b) { return b ^ ((b >> 3) & 0x70); }

__device__ __forceinline__ void cp_async16(uint32_t s, const void* g) {
    asm volatile("cp.async.cg.shared.global [%0], [%1], 16;" :: "r"(s), "l"(g));
}
__device__ __forceinline__ void cp_commit() {
    asm volatile("cp.async.commit_group;" ::: "memory");
}
__device__ __forceinline__ void cp_wait1() {
    asm volatile("cp.async.wait_group 1;" ::: "memory");
}

__device__ __forceinline__ void ldm_x4(uint32_t* r, uint32_t addr) {
    asm volatile("ldmatrix.sync.aligned.m8n8.x4.shared.b16 {%0,%1,%2,%3}, [%4];"
        : "=r"(r[0]), "=r"(r[1]), "=r"(r[2]), "=r"(r[3]) : "r"(addr));
}

__device__ __forceinline__ void mma_s8(int* c, const uint32_t* a, uint32_t b0, uint32_t b1) {
    asm volatile("mma.sync.aligned.m16n8k32.row.col.s32.s8.s8.s32 "
        "{%0,%1,%2,%3}, {%4,%5,%6,%7}, {%8,%9}, {%0,%1,%2,%3};"
        : "+r"(c[0]), "+r"(c[1]), "+r"(c[2]), "+r"(c[3])
        : "r"(a[0]), "r"(a[1]), "r"(a[2]), "r"(a[3]), "r"(b0), "r"(b1));
}

__device__ __forceinline__ int clamp127(int v) {
    return v < -127 ? -127 : (v > 127 ? 127 : v);
}
__device__ __forceinline__ uint32_t pack4(int a, int b, int c, int d) {
    return (uint32_t)(a & 0xFF) | ((uint32_t)(b & 0xFF) << 8) |
           ((uint32_t)(c & 0xFF) << 16) | ((uint32_t)(d & 0xFF) << 24);
}

// ------------------------- kernel 1: quantize x --------------------------
// one block (256 threads) per row of K_DIM floats
__global__ void __launch_bounds__(256) quant_x_kernel(const float* __restrict__ x) {
    const int row = blockIdx.x;
    const float4* xv = reinterpret_cast<const float4*>(x + (size_t)row * K_DIM);

    float4 v[4];
    float m = 0.f;
#pragma unroll
    for (int i = 0; i < 4; i++) {
        v[i] = xv[threadIdx.x * 4 + i];   // 16 consecutive floats per thread
        m = fmaxf(m, fmaxf(fmaxf(fabsf(v[i].x), fabsf(v[i].y)),
                           fmaxf(fabsf(v[i].z), fabsf(v[i].w))));
    }
#pragma unroll
    for (int o = 16; o; o >>= 1) m = fmaxf(m, __shfl_xor_sync(0xFFFFFFFFu, m, o));

    __shared__ float sm[8];
    if ((threadIdx.x & 31) == 0) sm[threadIdx.x >> 5] = m;
    __syncthreads();
    if (threadIdx.x < 32) {
        float t = (threadIdx.x < 8) ? sm[threadIdx.x] : 0.f;
#pragma unroll
        for (int o = 4; o; o >>= 1) t = fmaxf(t, __shfl_xor_sync(0xFFFFFFFFu, t, o));
        if (threadIdx.x == 0) sm[0] = t;
    }
    __syncthreads();
    float sx = sm[0] / 127.0f;
    if (sx == 0.f) sx = 1.0f;
    if (threadIdx.x == 0) g_sx[row] = sx;

    uint4 o;
    uint32_t q[4];
#pragma unroll
    for (int i = 0; i < 4; i++) {
        int q0 = clamp127(__float2int_rn(v[i].x / sx));
        int q1 = clamp127(__float2int_rn(v[i].y / sx));
        int q2 = clamp127(__float2int_rn(v[i].z / sx));
        int q3 = clamp127(__float2int_rn(v[i].w / sx));
        q[i] = pack4(q0, q1, q2, q3);
    }
    o.x = q[0]; o.y = q[1]; o.z = q[2]; o.w = q[3];
    reinterpret_cast<uint4*>(g_xq + (size_t)row * K_DIM)[threadIdx.x] = o;
}

// ------------------------- kernel 2: weights int32 -> int8 ---------------
__global__ void __launch_bounds__(256) quant_w_kernel(const int* __restrict__ w) {
    const long total16 = (long)N_DIM * K_DIM / 16;   // uint4 outputs
    long gid = blockIdx.x * 256L + threadIdx.x;
    long stride = gridDim.x * 256L;
    const int4* wv = reinterpret_cast<const int4*>(w);
    uint4* out = reinterpret_cast<uint4*>(g_wq);
    for (; gid < total16; gid += stride) {
        int4 a = wv[gid * 4 + 0];
        int4 b = wv[gid * 4 + 1];
        int4 c = wv[gid * 4 + 2];
        int4 d = wv[gid * 4 + 3];
        uint4 o;
        o.x = pack4(a.x, a.y, a.z, a.w);
        o.y = pack4(b.x, b.y, b.z, b.w);
        o.z = pack4(c.x, c.y, c.z, c.w);
        o.w = pack4(d.x, d.y, d.z, d.w);
        out[gid] = o;
    }
}

// ------------------------- kernel 3: int8 IMMA GEMM ----------------------
// 128x256 CTA tile, 8 warps (2 M x 4 N), 64x64 warp tiles,
// 3-stage cp.async pipeline, ldmatrix + mma.sync.m16n8k32.s8
__device__ __forceinline__ void load_stage(uint32_t sbase, int m0, int n0,
                                           int kblk, int tid) {
    const int kb = kblk * BK;
#pragma unroll
    for (int i = 0; i < 4; i++) {       // A: 128 rows x 128 B
        int id = tid + i * 256;
        int r = id >> 3, c = id & 7;
        const char* g = g_xq + (size_t)(m0 + r) * K_DIM + kb + c * 16;
        cp_async16(sbase + swz128((uint32_t)(r * 128 + c * 16)), g);
    }
#pragma unroll
    for (int i = 0; i < 8; i++) {       // B: 256 rows x 128 B
        int id = tid + i * 256;
        int r = id >> 3, c = id & 7;
        const char* g = g_wq + (size_t)(n0 + r) * K_DIM + kb + c * 16;
        cp_async16(sbase + A_SMEM + swz128((uint32_t)(r * 128 + c * 16)), g);
    }
}

__global__ void __launch_bounds__(256, 1) gemm_kernel(float* __restrict__ out,
                                                      const float* __restrict__ scale,
                                                      const float* __restrict__ bias) {
    extern __shared__ char smem[];
    const uint32_t sb = smem_u32(smem);
    const int tid = threadIdx.x;
    const int wid = tid >> 5;
    const int lane = tid & 31;
    const int n0 = blockIdx.x * BN;
    const int m0 = blockIdx.y * BM;
    const int wm = wid >> 2;            // 0..1
    const int wn = wid & 3;             // 0..3

    // ldmatrix per-lane addressing
    const int q = lane >> 3;            // matrix index 0..3
    const int rw = lane & 7;            // row within 8x8 matrix
    const uint32_t mask = (uint32_t)rw << 4;      // SW128 swizzle of the row
    const int kbA = (q >> 1) * 16;      // A: matrices {rows0-7 k0-15, rows8-15 k0-15, rows0-7 k16-31, rows8-15 k16-31}
    const int kbB = (q & 1) * 16;       // B: matrices {n0-7 k0-15, n0-7 k16-31, n8-15 k0-15, n8-15 k16-31}
    uint32_t rowA[4], rowB[4];
#pragma unroll
    for (int mi = 0; mi < 4; mi++)
        rowA[mi] = (uint32_t)((wm * 64 + mi * 16 + (q & 1) * 8 + rw) * 128);
#pragma unroll
    for (int nj = 0; nj < 4; nj++)
        rowB[nj] = (uint32_t)(A_SMEM + (wn * 64 + nj * 16 + (q >> 1) * 8 + rw) * 128);

    int acc[4][8][4];
#pragma unroll
    for (int mi = 0; mi < 4; mi++)
#pragma unroll
        for (int nj = 0; nj < 8; nj++)
#pragma unroll
            for (int t = 0; t < 4; t++) acc[mi][nj][t] = 0;

    // prologue
    load_stage(sb + 0 * STAGE_BYTES, m0, n0, 0, tid); cp_commit();
    load_stage(sb + 1 * STAGE_BYTES, m0, n0, 1, tid); cp_commit();

    for (int k = 0; k < KSTEPS; k++) {
        cp_wait1();
        __syncthreads();
        if (k + 2 < KSTEPS)
            load_stage(sb + ((k + 2) % STAGES) * STAGE_BYTES, m0, n0, k + 2, tid);
        cp_commit();

        const uint32_t stg = sb + (k % STAGES) * STAGE_BYTES;
#pragma unroll
        for (int ks = 0; ks < 4; ks++) {
            const uint32_t koffA = (uint32_t)((ks * 32 + kbA) ^ (int)mask);
            const uint32_t koffB = (uint32_t)((ks * 32 + kbB) ^ (int)mask);
            uint32_t a[4][4], b[4][4];
#pragma unroll
            for (int mi = 0; mi < 4; mi++) ldm_x4(a[mi], stg + rowA[mi] + koffA);
#pragma unroll
            for (int nj = 0; nj < 4; nj++) ldm_x4(b[nj], stg + rowB[nj] + koffB);
#pragma unroll
            for (int mi = 0; mi < 4; mi++) {
#pragma unroll
                for (int nj = 0; nj < 4; nj++) {
                    mma_s8(acc[mi][2 * nj + 0], a[mi], b[nj][0], b[nj][1]);
                    mma_s8(acc[mi][2 * nj + 1], a[mi], b[nj][2], b[nj][3]);
                }
            }
        }
    }

    // ------------- epilogue: dequant + bias, float2 stores ---------------
    const int nbase = n0 + wn * 64;
#pragma unroll
    for (int mi = 0; mi < 4; mi++) {
        const int mlo = m0 + wm * 64 + mi * 16 + (lane >> 2);
        const int mhi = mlo + 8;
        const float slo = g_sx[mlo];
        const float shi = g_sx[mhi];
        float* orow_lo = out + (size_t)mlo * N_DIM + nbase;
        float* orow_hi = out + (size_t)mhi * N_DIM + nbase;
#pragma unroll
        for (int nj = 0; nj < 8; nj++) {
            const int n = nj * 8 + 2 * (lane & 3);
            const float2 sc = *reinterpret_cast<const float2*>(scale + nbase + n);
            const float2 bi = *reinterpret_cast<const float2*>(bias + nbase + n);
            const int* c = acc[mi][nj];
            float2 vlo, vhi;
            vlo.x = fmaf(__int2float_rn(c[0]) * slo, sc.x, bi.x);
            vlo.y = fmaf(__int2float_rn(c[1]) * slo, sc.y, bi.y);
            vhi.x = fmaf(__int2float_rn(c[2]) * shi, sc.x, bi.x);
            vhi.y = fmaf(__int2float_rn(c[3]) * shi, sc.y, bi.y);
            *reinterpret_cast<float2*>(orow_lo + n) = vlo;
            *reinterpret_cast<float2*>(orow_hi + n) = vhi;
        }
    }
}

// ------------------------- launch ---------------------------------------
extern "C" void kernel_launch(void* const* d_in, const int* in_sizes, int n_in,
                              void* d_out, int out_size) {
    const float* x = (const float*)d_in[0];
    const int* w = (const int*)d_in[1];
    const float* scale = (const float*)d_in[2];
    const float* bias = (const float*)d_in[3];
    float* out = (float*)d_out;

    const int M = in_sizes[0] / K_DIM;   // 8192

    static int smem_set = 0;
    if (!smem_set) {
        cudaFuncSetAttribute(gemm_kernel, cudaFuncAttributeMaxDynamicSharedMemorySize,
                             GEMM_SMEM);
        smem_set = 1;
    }

    quant_x_kernel<<<M, 256>>>(x);
    quant_w_kernel<<<16384, 256>>>(w);
    gemm_kernel<<<dim3(N_DIM / BN, M / BM), 256, GEMM_SMEM>>>(out, scale, bias);
}

// round 3
// speedup vs baseline: 2.6908x; 2.6908x over previous
#include <cuda_runtime.h>
#include <cuda_bf16.h>
#include <stdint.h>

#define K_DIM 4096
#define N_DIM 16384
#define M_MAX 8192

#define BM 128
#define BN 256
#define BK 64                        // bf16 elems of K per stage (128 bytes)
#define STAGES 3
#define KSTEPS (K_DIM / BK)          // 64
#define A_SMEM (BM * 128)            // 16384 bytes
#define B_SMEM (BN * 128)            // 32768 bytes
#define STAGE_BYTES (A_SMEM + B_SMEM)    // 49152
#define GEMM_SMEM (STAGES * STAGE_BYTES) // 147456
#define MSPLIT 4                     // gemm launches (profiling + same perf)

// ------------------------- scratch (device globals; no runtime alloc) ---
__device__ __nv_bfloat16 g_xq[(size_t)M_MAX * K_DIM];   // 64 MB bf16 x
__device__ __nv_bfloat16 g_wq[(size_t)N_DIM * K_DIM];   // 128 MB bf16 w
__device__ float g_sx[M_MAX];

// ------------------------- helpers --------------------------------------
__device__ __forceinline__ uint32_t smem_u32(const void* p) {
    uint32_t a;
    asm("{ .reg .u64 t; cvta.to.shared.u64 t, %1; cvt.u32.u64 %0, t; }"
        : "=r"(a) : "l"(p));
    return a;
}
__device__ __forceinline__ uint32_t swz128(uint32_t b) { return b ^ ((b >> 3) & 0x70); }

__device__ __forceinline__ void cp_async16(uint32_t s, const void* g) {
    asm volatile("cp.async.cg.shared.global [%0], [%1], 16;" :: "r"(s), "l"(g));
}
__device__ __forceinline__ void cp_commit() {
    asm volatile("cp.async.commit_group;" ::: "memory");
}
__device__ __forceinline__ void cp_wait1() {
    asm volatile("cp.async.wait_group 1;" ::: "memory");
}

__device__ __forceinline__ void ldm_x4(uint32_t* r, uint32_t addr) {
    asm volatile("ldmatrix.sync.aligned.m8n8.x4.shared.b16 {%0,%1,%2,%3}, [%4];"
        : "=r"(r[0]), "=r"(r[1]), "=r"(r[2]), "=r"(r[3]) : "r"(addr));
}

// bf16 HMMA: D(f32) += A(bf16) * B(bf16), m16n8k16
__device__ __forceinline__ void mma_bf16(float* c, const uint32_t* a, uint32_t b0, uint32_t b1) {
    asm volatile("mma.sync.aligned.m16n8k16.row.col.f32.bf16.bf16.f32 "
        "{%0,%1,%2,%3}, {%4,%5,%6,%7}, {%8,%9}, {%0,%1,%2,%3};"
        : "+f"(c[0]), "+f"(c[1]), "+f"(c[2]), "+f"(c[3])
        : "r"(a[0]), "r"(a[1]), "r"(a[2]), "r"(a[3]), "r"(b0), "r"(b1));
}

__device__ __forceinline__ uint32_t pack_bf16x2(float a, float b) {
    __nv_bfloat162 h = __floats2bfloat162_rn(a, b);
    return *reinterpret_cast<uint32_t*>(&h);
}

// ------------------------- kernel 1: quantize x -> bf16 ------------------
// one block (256 threads) per row of K_DIM floats
__global__ void __launch_bounds__(256) quant_x_kernel(const float* __restrict__ x) {
    const int row = blockIdx.x;
    const float4* xv = reinterpret_cast<const float4*>(x + (size_t)row * K_DIM);

    float4 v[4];
    float m = 0.f;
#pragma unroll
    for (int i = 0; i < 4; i++) {
        v[i] = xv[threadIdx.x * 4 + i];   // 16 consecutive floats per thread
        m = fmaxf(m, fmaxf(fmaxf(fabsf(v[i].x), fabsf(v[i].y)),
                           fmaxf(fabsf(v[i].z), fabsf(v[i].w))));
    }
#pragma unroll
    for (int o = 16; o; o >>= 1) m = fmaxf(m, __shfl_xor_sync(0xFFFFFFFFu, m, o));

    __shared__ float sm[8];
    if ((threadIdx.x & 31) == 0) sm[threadIdx.x >> 5] = m;
    __syncthreads();
    if (threadIdx.x < 32) {
        float t = (threadIdx.x < 8) ? sm[threadIdx.x] : 0.f;
#pragma unroll
        for (int o = 4; o; o >>= 1) t = fmaxf(t, __shfl_xor_sync(0xFFFFFFFFu, t, o));
        if (threadIdx.x == 0) sm[0] = t;
    }
    __syncthreads();
    float sx = sm[0] / 127.0f;
    if (sx == 0.f) sx = 1.0f;
    if (threadIdx.x == 0) g_sx[row] = sx;

    uint4 o1, o2;
    float q[16];
#pragma unroll
    for (int i = 0; i < 4; i++) {
        q[4 * i + 0] = fminf(fmaxf(rintf(v[i].x / sx), -127.f), 127.f);
        q[4 * i + 1] = fminf(fmaxf(rintf(v[i].y / sx), -127.f), 127.f);
        q[4 * i + 2] = fminf(fmaxf(rintf(v[i].z / sx), -127.f), 127.f);
        q[4 * i + 3] = fminf(fmaxf(rintf(v[i].w / sx), -127.f), 127.f);
    }
    o1.x = pack_bf16x2(q[0], q[1]);  o1.y = pack_bf16x2(q[2], q[3]);
    o1.z = pack_bf16x2(q[4], q[5]);  o1.w = pack_bf16x2(q[6], q[7]);
    o2.x = pack_bf16x2(q[8], q[9]);  o2.y = pack_bf16x2(q[10], q[11]);
    o2.z = pack_bf16x2(q[12], q[13]); o2.w = pack_bf16x2(q[14], q[15]);
    uint4* outp = reinterpret_cast<uint4*>(g_xq + (size_t)row * K_DIM);
    outp[threadIdx.x * 2 + 0] = o1;
    outp[threadIdx.x * 2 + 1] = o2;
}

// ------------------------- kernel 2: weights int32 -> bf16 ---------------
__global__ void __launch_bounds__(256) quant_w_kernel(const int* __restrict__ w) {
    const long total8 = (long)N_DIM * K_DIM / 8;     // uint4 (8 bf16) outputs
    long gid = blockIdx.x * 256L + threadIdx.x;
    long stride = gridDim.x * 256L;
    const int4* wv = reinterpret_cast<const int4*>(w);
    uint4* out = reinterpret_cast<uint4*>(g_wq);
    for (; gid < total8; gid += stride) {
        int4 a = wv[gid * 2 + 0];
        int4 b = wv[gid * 2 + 1];
        uint4 o;
        o.x = pack_bf16x2((float)a.x, (float)a.y);
        o.y = pack_bf16x2((float)a.z, (float)a.w);
        o.z = pack_bf16x2((float)b.x, (float)b.y);
        o.w = pack_bf16x2((float)b.z, (float)b.w);
        out[gid] = o;
    }
}

// ------------------------- kernel 3: bf16 HMMA GEMM ----------------------
// 128x256 CTA tile, 8 warps (2 M x 4 N), 64x64 warp tiles,
// 3-stage cp.async pipeline, ldmatrix + mma.sync.m16n8k16.bf16
__device__ __forceinline__ void load_stage(uint32_t sbase, int m0, int n0,
                                           int kblk, int tid) {
    const int kb = kblk * 128;          // bytes along K (BK bf16 * 2)
#pragma unroll
    for (int i = 0; i < 4; i++) {       // A: 128 rows x 128 B
        int id = tid + i * 256;
        int r = id >> 3, c = id & 7;
        const char* g = reinterpret_cast<const char*>(g_xq + (size_t)(m0 + r) * K_DIM) + kb + c * 16;
        cp_async16(sbase + swz128((uint32_t)(r * 128 + c * 16)), g);
    }
#pragma unroll
    for (int i = 0; i < 8; i++) {       // B: 256 rows x 128 B
        int id = tid + i * 256;
        int r = id >> 3, c = id & 7;
        const char* g = reinterpret_cast<const char*>(g_wq + (size_t)(n0 + r) * K_DIM) + kb + c * 16;
        cp_async16(sbase + A_SMEM + swz128((uint32_t)(r * 128 + c * 16)), g);
    }
}

__global__ void __launch_bounds__(256, 1) gemm_kernel(float* __restrict__ out,
                                                      const float* __restrict__ scale,
                                                      const float* __restrict__ bias,
                                                      int m_off) {
    extern __shared__ char smem[];
    const uint32_t sb = smem_u32(smem);
    const int tid = threadIdx.x;
    const int wid = tid >> 5;
    const int lane = tid & 31;
    const int n0 = blockIdx.x * BN;
    const int m0 = m_off + blockIdx.y * BM;
    const int wm = wid >> 2;            // 0..1
    const int wn = wid & 3;             // 0..3

    // ldmatrix per-lane addressing (q = matrix index 0..3, rw = row in 8x8)
    const int q = lane >> 3;
    const int rw = lane & 7;
    const uint32_t mask = (uint32_t)rw << 4;      // SW128 swizzle for this row
    const int kbA = (q >> 1) * 16;      // A mats: {m0-7/k0-7, m8-15/k0-7, m0-7/k8-15, m8-15/k8-15}
    const int kbB = (q & 1) * 16;       // B mats: {n0-7/k0-7, n0-7/k8-15, n8-15/k0-7, n8-15/k8-15}
    uint32_t rowA[4], rowB[4];
#pragma unroll
    for (int mi = 0; mi < 4; mi++)
        rowA[mi] = (uint32_t)((wm * 64 + mi * 16 + (q & 1) * 8 + rw) * 128);
#pragma unroll
    for (int nj = 0; nj < 4; nj++)
        rowB[nj] = (uint32_t)(A_SMEM + (wn * 64 + nj * 16 + (q >> 1) * 8 + rw) * 128);

    float acc[4][8][4];
#pragma unroll
    for (int mi = 0; mi < 4; mi++)
#pragma unroll
        for (int nj = 0; nj < 8; nj++)
#pragma unroll
            for (int t = 0; t < 4; t++) acc[mi][nj][t] = 0.f;

    // prologue
    load_stage(sb + 0 * STAGE_BYTES, m0, n0, 0, tid); cp_commit();
    load_stage(sb + 1 * STAGE_BYTES, m0, n0, 1, tid); cp_commit();

    for (int k = 0; k < KSTEPS; k++) {
        cp_wait1();
        __syncthreads();
        if (k + 2 < KSTEPS)
            load_stage(sb + ((k + 2) % STAGES) * STAGE_BYTES, m0, n0, k + 2, tid);
        cp_commit();

        const uint32_t stg = sb + (k % STAGES) * STAGE_BYTES;
#pragma unroll
        for (int ks = 0; ks < 4; ks++) {          // 4 x k16 per 64-elem stage
            const uint32_t koffA = (uint32_t)((ks * 32 + kbA) ^ (int)mask);
            const uint32_t koffB = (uint32_t)((ks * 32 + kbB) ^ (int)mask);
            uint32_t a[4][4], b[4][4];
#pragma unroll
            for (int mi = 0; mi < 4; mi++) ldm_x4(a[mi], stg + rowA[mi] + koffA);
#pragma unroll
            for (int nj = 0; nj < 4; nj++) ldm_x4(b[nj], stg + rowB[nj] + koffB);
#pragma unroll
            for (int mi = 0; mi < 4; mi++) {
#pragma unroll
                for (int nj = 0; nj < 4; nj++) {
                    mma_bf16(acc[mi][2 * nj + 0], a[mi], b[nj][0], b[nj][1]);
                    mma_bf16(acc[mi][2 * nj + 1], a[mi], b[nj][2], b[nj][3]);
                }
            }
        }
    }

    // ------------- epilogue: dequant + bias, float2 stores ---------------
    const int nbase = n0 + wn * 64;
#pragma unroll
    for (int mi = 0; mi < 4; mi++) {
        const int mlo = m0 + wm * 64 + mi * 16 + (lane >> 2);
        const int mhi = mlo + 8;
        const float slo = g_sx[mlo];
        const float shi = g_sx[mhi];
        float* orow_lo = out + (size_t)mlo * N_DIM + nbase;
        float* orow_hi = out + (size_t)mhi * N_DIM + nbase;
#pragma unroll
        for (int nj = 0; nj < 8; nj++) {
            const int n = nj * 8 + 2 * (lane & 3);
            const float2 sc = *reinterpret_cast<const float2*>(scale + nbase + n);
            const float2 bi = *reinterpret_cast<const float2*>(bias + nbase + n);
            const float* c = acc[mi][nj];
            float2 vlo, vhi;
            vlo.x = fmaf(c[0] * slo, sc.x, bi.x);
            vlo.y = fmaf(c[1] * slo, sc.y, bi.y);
            vhi.x = fmaf(c[2] * shi, sc.x, bi.x);
            vhi.y = fmaf(c[3] * shi, sc.y, bi.y);
            *reinterpret_cast<float2*>(orow_lo + n) = vlo;
            *reinterpret_cast<float2*>(orow_hi + n) = vhi;
        }
    }
}

// ------------------------- launch ---------------------------------------
extern "C" void kernel_launch(void* const* d_in, const int* in_sizes, int n_in,
                              void* d_out, int out_size) {
    const float* x = (const float*)d_in[0];
    const int* w = (const int*)d_in[1];
    const float* scale = (const float*)d_in[2];
    const float* bias = (const float*)d_in[3];
    float* out = (float*)d_out;

    const int M = in_sizes[0] / K_DIM;   // 8192

    static int smem_set = 0;
    if (!smem_set) {
        cudaFuncSetAttribute(gemm_kernel, cudaFuncAttributeMaxDynamicSharedMemorySize,
                             GEMM_SMEM);
        smem_set = 1;
    }

    quant_x_kernel<<<M, 256>>>(x);
    quant_w_kernel<<<16384, 256>>>(w);
    const int mchunk = M / MSPLIT;       // 2048 rows per gemm launch
    for (int s = 0; s < MSPLIT; s++) {
        gemm_kernel<<<dim3(N_DIM / BN, mchunk / BM), 256, GEMM_SMEM>>>(
            out, scale, bias, s * mchunk);
    }
}

// round 4
// speedup vs baseline: 2.8296x; 1.0516x over previous
#include <cuda_runtime.h>
#include <cuda_bf16.h>
#include <stdint.h>

#define K_DIM 4096
#define N_DIM 16384
#define M_MAX 8192

#define BM 128
#define BN 256
#define BK 64                        // bf16 elems of K per stage (128 bytes)
#define STAGES 4
#define KSTEPS (K_DIM / BK)          // 64
#define A_SMEM (BM * 128)            // 16384 bytes
#define B_SMEM (BN * 128)            // 32768 bytes
#define STAGE_BYTES (A_SMEM + B_SMEM)    // 49152
#define GEMM_SMEM (STAGES * STAGE_BYTES) // 196608

// ------------------------- scratch (device globals; no runtime alloc) ---
__device__ __nv_bfloat16 g_xq[(size_t)M_MAX * K_DIM];   // 64 MB bf16 x
__device__ __nv_bfloat16 g_wq[(size_t)N_DIM * K_DIM];   // 128 MB bf16 w
__device__ float g_sx[M_MAX];

// ------------------------- helpers --------------------------------------
__device__ __forceinline__ uint32_t smem_u32(const void* p) {
    uint32_t a;
    asm("{ .reg .u64 t; cvta.to.shared.u64 t, %1; cvt.u32.u64 %0, t; }"
        : "=r"(a) : "l"(p));
    return a;
}
__device__ __forceinline__ uint32_t swz128(uint32_t b) { return b ^ ((b >> 3) & 0x70); }

__device__ __forceinline__ void cp_async16(uint32_t s, const void* g) {
    asm volatile("cp.async.cg.shared.global [%0], [%1], 16;" :: "r"(s), "l"(g));
}
__device__ __forceinline__ void cp_commit() {
    asm volatile("cp.async.commit_group;" ::: "memory");
}
__device__ __forceinline__ void cp_wait2() {
    asm volatile("cp.async.wait_group 2;" ::: "memory");
}

__device__ __forceinline__ void ldm_x4(uint32_t* r, uint32_t addr) {
    asm volatile("ldmatrix.sync.aligned.m8n8.x4.shared.b16 {%0,%1,%2,%3}, [%4];"
        : "=r"(r[0]), "=r"(r[1]), "=r"(r[2]), "=r"(r[3]) : "r"(addr));
}

// bf16 HMMA: D(f32) += A(bf16) * B(bf16), m16n8k16
__device__ __forceinline__ void mma_bf16(float* c, const uint32_t* a, uint32_t b0, uint32_t b1) {
    asm volatile("mma.sync.aligned.m16n8k16.row.col.f32.bf16.bf16.f32 "
        "{%0,%1,%2,%3}, {%4,%5,%6,%7}, {%8,%9}, {%0,%1,%2,%3};"
        : "+f"(c[0]), "+f"(c[1]), "+f"(c[2]), "+f"(c[3])
        : "r"(a[0]), "r"(a[1]), "r"(a[2]), "r"(a[3]), "r"(b0), "r"(b1));
}

__device__ __forceinline__ uint32_t pack_bf16x2(float a, float b) {
    __nv_bfloat162 h = __floats2bfloat162_rn(a, b);
    return *reinterpret_cast<uint32_t*>(&h);
}

// ------------------------- kernel 1: quantize x -> bf16 ------------------
// one block (256 threads) per row of K_DIM floats
__global__ void __launch_bounds__(256) quant_x_kernel(const float* __restrict__ x) {
    const int row = blockIdx.x;
    const float4* xv = reinterpret_cast<const float4*>(x + (size_t)row * K_DIM);

    float4 v[4];
    float m = 0.f;
#pragma unroll
    for (int i = 0; i < 4; i++) {
        v[i] = xv[threadIdx.x * 4 + i];   // 16 consecutive floats per thread
        m = fmaxf(m, fmaxf(fmaxf(fabsf(v[i].x), fabsf(v[i].y)),
                           fmaxf(fabsf(v[i].z), fabsf(v[i].w))));
    }
#pragma unroll
    for (int o = 16; o; o >>= 1) m = fmaxf(m, __shfl_xor_sync(0xFFFFFFFFu, m, o));

    __shared__ float sm[8];
    if ((threadIdx.x & 31) == 0) sm[threadIdx.x >> 5] = m;
    __syncthreads();
    if (threadIdx.x < 32) {
        float t = (threadIdx.x < 8) ? sm[threadIdx.x] : 0.f;
#pragma unroll
        for (int o = 4; o; o >>= 1) t = fmaxf(t, __shfl_xor_sync(0xFFFFFFFFu, t, o));
        if (threadIdx.x == 0) sm[0] = t;
    }
    __syncthreads();
    float sx = sm[0] / 127.0f;
    if (sx == 0.f) sx = 1.0f;
    if (threadIdx.x == 0) g_sx[row] = sx;

    uint4 o1, o2;
    float q[16];
#pragma unroll
    for (int i = 0; i < 4; i++) {
        q[4 * i + 0] = fminf(fmaxf(rintf(v[i].x / sx), -127.f), 127.f);
        q[4 * i + 1] = fminf(fmaxf(rintf(v[i].y / sx), -127.f), 127.f);
        q[4 * i + 2] = fminf(fmaxf(rintf(v[i].z / sx), -127.f), 127.f);
        q[4 * i + 3] = fminf(fmaxf(rintf(v[i].w / sx), -127.f), 127.f);
    }
    o1.x = pack_bf16x2(q[0], q[1]);  o1.y = pack_bf16x2(q[2], q[3]);
    o1.z = pack_bf16x2(q[4], q[5]);  o1.w = pack_bf16x2(q[6], q[7]);
    o2.x = pack_bf16x2(q[8], q[9]);  o2.y = pack_bf16x2(q[10], q[11]);
    o2.z = pack_bf16x2(q[12], q[13]); o2.w = pack_bf16x2(q[14], q[15]);
    uint4* outp = reinterpret_cast<uint4*>(g_xq + (size_t)row * K_DIM);
    outp[threadIdx.x * 2 + 0] = o1;
    outp[threadIdx.x * 2 + 1] = o2;
}

// ------------------------- kernel 2: weights int32 -> bf16 ---------------
__global__ void __launch_bounds__(256) quant_w_kernel(const int* __restrict__ w) {
    const long total8 = (long)N_DIM * K_DIM / 8;     // uint4 (8 bf16) outputs
    long gid = blockIdx.x * 256L + threadIdx.x;
    long stride = gridDim.x * 256L;
    const int4* wv = reinterpret_cast<const int4*>(w);
    uint4* out = reinterpret_cast<uint4*>(g_wq);
    for (; gid < total8; gid += stride) {
        int4 a = wv[gid * 2 + 0];
        int4 b = wv[gid * 2 + 1];
        uint4 o;
        o.x = pack_bf16x2((float)a.x, (float)a.y);
        o.y = pack_bf16x2((float)a.z, (float)a.w);
        o.z = pack_bf16x2((float)b.x, (float)b.y);
        o.w = pack_bf16x2((float)b.z, (float)b.w);
        out[gid] = o;
    }
}

// ------------------------- kernel 3: bf16 HMMA GEMM ----------------------
// 128x256 CTA tile, 8 warps (2 M x 4 N), 64x64 warp tiles,
// 4-stage cp.async pipeline (wait_group 2), ldmatrix + mma.m16n8k16.bf16
__device__ __forceinline__ void load_stage(uint32_t sbase, int m0, int n0,
                                           int kblk, int tid) {
    const int kb = kblk * 128;          // bytes along K (BK bf16 * 2)
#pragma unroll
    for (int i = 0; i < 4; i++) {       // A: 128 rows x 128 B
        int id = tid + i * 256;
        int r = id >> 3, c = id & 7;
        const char* g = reinterpret_cast<const char*>(g_xq + (size_t)(m0 + r) * K_DIM) + kb + c * 16;
        cp_async16(sbase + swz128((uint32_t)(r * 128 + c * 16)), g);
    }
#pragma unroll
    for (int i = 0; i < 8; i++) {       // B: 256 rows x 128 B
        int id = tid + i * 256;
        int r = id >> 3, c = id & 7;
        const char* g = reinterpret_cast<const char*>(g_wq + (size_t)(n0 + r) * K_DIM) + kb + c * 16;
        cp_async16(sbase + A_SMEM + swz128((uint32_t)(r * 128 + c * 16)), g);
    }
}

__global__ void __launch_bounds__(256, 1) gemm_kernel(float* __restrict__ out,
                                                      const float* __restrict__ scale,
                                                      const float* __restrict__ bias) {
    extern __shared__ char smem[];
    const uint32_t sb = smem_u32(smem);
    const int tid = threadIdx.x;
    const int wid = tid >> 5;
    const int lane = tid & 31;
    const int n0 = blockIdx.x * BN;
    const int m0 = blockIdx.y * BM;
    const int wm = wid >> 2;            // 0..1
    const int wn = wid & 3;             // 0..3

    // ldmatrix per-lane addressing (q = matrix index 0..3, rw = row in 8x8)
    const int q = lane >> 3;
    const int rw = lane & 7;
    const uint32_t mask = (uint32_t)rw << 4;      // SW128 swizzle for this row
    const int kbA = (q >> 1) * 16;      // A mats: {m0-7/k0-7, m8-15/k0-7, m0-7/k8-15, m8-15/k8-15}
    const int kbB = (q & 1) * 16;       // B mats: {n0-7/k0-7, n0-7/k8-15, n8-15/k0-7, n8-15/k8-15}
    uint32_t rowA[4], rowB[4];
#pragma unroll
    for (int mi = 0; mi < 4; mi++)
        rowA[mi] = (uint32_t)((wm * 64 + mi * 16 + (q & 1) * 8 + rw) * 128);
#pragma unroll
    for (int nj = 0; nj < 4; nj++)
        rowB[nj] = (uint32_t)(A_SMEM + (wn * 64 + nj * 16 + (q >> 1) * 8 + rw) * 128);

    float acc[4][8][4];
#pragma unroll
    for (int mi = 0; mi < 4; mi++)
#pragma unroll
        for (int nj = 0; nj < 8; nj++)
#pragma unroll
            for (int t = 0; t < 4; t++) acc[mi][nj][t] = 0.f;

    // prologue: stages 0..2 in flight
    load_stage(sb + 0 * STAGE_BYTES, m0, n0, 0, tid); cp_commit();
    load_stage(sb + 1 * STAGE_BYTES, m0, n0, 1, tid); cp_commit();
    load_stage(sb + 2 * STAGE_BYTES, m0, n0, 2, tid); cp_commit();

    for (int k = 0; k < KSTEPS; k++) {
        cp_wait2();                      // stage k complete (oldest pending)
        __syncthreads();                 // all warps past compute of k-1
        if (k + 3 < KSTEPS)
            load_stage(sb + ((k + 3) % STAGES) * STAGE_BYTES, m0, n0, k + 3, tid);
        cp_commit();                     // unconditional: keeps group accounting

        const uint32_t stg = sb + (k % STAGES) * STAGE_BYTES;
#pragma unroll
        for (int ks = 0; ks < 4; ks++) {          // 4 x k16 per 64-elem stage
            const uint32_t koffA = (uint32_t)((ks * 32 + kbA) ^ (int)mask);
            const uint32_t koffB = (uint32_t)((ks * 32 + kbB) ^ (int)mask);
            uint32_t a[4][4], b[4][4];
#pragma unroll
            for (int mi = 0; mi < 4; mi++) ldm_x4(a[mi], stg + rowA[mi] + koffA);
#pragma unroll
            for (int nj = 0; nj < 4; nj++) ldm_x4(b[nj], stg + rowB[nj] + koffB);
#pragma unroll
            for (int mi = 0; mi < 4; mi++) {
#pragma unroll
                for (int nj = 0; nj < 4; nj++) {
                    mma_bf16(acc[mi][2 * nj + 0], a[mi], b[nj][0], b[nj][1]);
                    mma_bf16(acc[mi][2 * nj + 1], a[mi], b[nj][2], b[nj][3]);
                }
            }
        }
    }

    // ------------- epilogue: dequant + bias, float2 stores ---------------
    const int nbase = n0 + wn * 64;
#pragma unroll
    for (int mi = 0; mi < 4; mi++) {
        const int mlo = m0 + wm * 64 + mi * 16 + (lane >> 2);
        const int mhi = mlo + 8;
        const float slo = g_sx[mlo];
        const float shi = g_sx[mhi];
        float* orow_lo = out + (size_t)mlo * N_DIM + nbase;
        float* orow_hi = out + (size_t)mhi * N_DIM + nbase;
#pragma unroll
        for (int nj = 0; nj < 8; nj++) {
            const int n = nj * 8 + 2 * (lane & 3);
            const float2 sc = *reinterpret_cast<const float2*>(scale + nbase + n);
            const float2 bi = *reinterpret_cast<const float2*>(bias + nbase + n);
            const float* c = acc[mi][nj];
            float2 vlo, vhi;
            vlo.x = fmaf(c[0] * slo, sc.x, bi.x);
            vlo.y = fmaf(c[1] * slo, sc.y, bi.y);
            vhi.x = fmaf(c[2] * shi, sc.x, bi.x);
            vhi.y = fmaf(c[3] * shi, sc.y, bi.y);
            *reinterpret_cast<float2*>(orow_lo + n) = vlo;
            *reinterpret_cast<float2*>(orow_hi + n) = vhi;
        }
    }
}

// ------------------------- launch ---------------------------------------
extern "C" void kernel_launch(void* const* d_in, const int* in_sizes, int n_in,
                              void* d_out, int out_size) {
    const float* x = (const float*)d_in[0];
    const int* w = (const int*)d_in[1];
    const float* scale = (const float*)d_in[2];
    const float* bias = (const float*)d_in[3];
    float* out = (float*)d_out;

    const int M = in_sizes[0] / K_DIM;   // 8192

    static int smem_set = 0;
    if (!smem_set) {
        cudaFuncSetAttribute(gemm_kernel, cudaFuncAttributeMaxDynamicSharedMemorySize,
                             GEMM_SMEM);
        smem_set = 1;
    }

    quant_x_kernel<<<M, 256>>>(x);
    quant_w_kernel<<<16384, 256>>>(w);
    gemm_kernel<<<dim3(N_DIM / BN, M / BM), 256, GEMM_SMEM>>>(out, scale, bias);
}

// round 5
// speedup vs baseline: 2.9094x; 1.0282x over previous
#include <cuda_runtime.h>
#include <cuda_bf16.h>
#include <stdint.h>

#define K_DIM 4096
#define N_DIM 16384
#define M_MAX 8192

#define BM 128
#define BN 256
#define BK 64                        // bf16 elems of K per stage (128 bytes)
#define STAGES 4
#define KSTEPS (K_DIM / BK)          // 64
#define A_SMEM (BM * 128)            // 16384 bytes
#define B_SMEM (BN * 128)            // 32768 bytes
#define STAGE_BYTES (A_SMEM + B_SMEM)    // 49152
#define GEMM_SMEM (STAGES * STAGE_BYTES) // 196608
#define GTHREADS 512

// ------------------------- scratch (device globals; no runtime alloc) ---
__device__ __nv_bfloat16 g_xq[(size_t)M_MAX * K_DIM];   // 64 MB bf16 x
__device__ __nv_bfloat16 g_wq[(size_t)N_DIM * K_DIM];   // 128 MB bf16 w
__device__ float g_sx[M_MAX];

// ------------------------- helpers --------------------------------------
__device__ __forceinline__ uint32_t smem_u32(const void* p) {
    uint32_t a;
    asm("{ .reg .u64 t; cvta.to.shared.u64 t, %1; cvt.u32.u64 %0, t; }"
        : "=r"(a) : "l"(p));
    return a;
}
__device__ __forceinline__ uint32_t swz128(uint32_t b) { return b ^ ((b >> 3) & 0x70); }

__device__ __forceinline__ void cp_async16(uint32_t s, const void* g) {
    asm volatile("cp.async.cg.shared.global [%0], [%1], 16;" :: "r"(s), "l"(g));
}
__device__ __forceinline__ void cp_commit() {
    asm volatile("cp.async.commit_group;" ::: "memory");
}
__device__ __forceinline__ void cp_wait2() {
    asm volatile("cp.async.wait_group 2;" ::: "memory");
}

__device__ __forceinline__ void ldm_x4(uint32_t* r, uint32_t addr) {
    asm volatile("ldmatrix.sync.aligned.m8n8.x4.shared.b16 {%0,%1,%2,%3}, [%4];"
        : "=r"(r[0]), "=r"(r[1]), "=r"(r[2]), "=r"(r[3]) : "r"(addr));
}

// bf16 HMMA: D(f32) += A(bf16) * B(bf16), m16n8k16
__device__ __forceinline__ void mma_bf16(float* c, const uint32_t* a, uint32_t b0, uint32_t b1) {
    asm volatile("mma.sync.aligned.m16n8k16.row.col.f32.bf16.bf16.f32 "
        "{%0,%1,%2,%3}, {%4,%5,%6,%7}, {%8,%9}, {%0,%1,%2,%3};"
        : "+f"(c[0]), "+f"(c[1]), "+f"(c[2]), "+f"(c[3])
        : "r"(a[0]), "r"(a[1]), "r"(a[2]), "r"(a[3]), "r"(b0), "r"(b1));
}

__device__ __forceinline__ uint32_t pack_bf16x2(float a, float b) {
    __nv_bfloat162 h = __floats2bfloat162_rn(a, b);
    return *reinterpret_cast<uint32_t*>(&h);
}

// ------------------------- kernel 1: quantize x -> bf16 ------------------
__global__ void __launch_bounds__(256) quant_x_kernel(const float* __restrict__ x) {
    const int row = blockIdx.x;
    const float4* xv = reinterpret_cast<const float4*>(x + (size_t)row * K_DIM);

    float4 v[4];
    float m = 0.f;
#pragma unroll
    for (int i = 0; i < 4; i++) {
        v[i] = xv[threadIdx.x * 4 + i];   // 16 consecutive floats per thread
        m = fmaxf(m, fmaxf(fmaxf(fabsf(v[i].x), fabsf(v[i].y)),
                           fmaxf(fabsf(v[i].z), fabsf(v[i].w))));
    }
#pragma unroll
    for (int o = 16; o; o >>= 1) m = fmaxf(m, __shfl_xor_sync(0xFFFFFFFFu, m, o));

    __shared__ float sm[8];
    if ((threadIdx.x & 31) == 0) sm[threadIdx.x >> 5] = m;
    __syncthreads();
    if (threadIdx.x < 32) {
        float t = (threadIdx.x < 8) ? sm[threadIdx.x] : 0.f;
#pragma unroll
        for (int o = 4; o; o >>= 1) t = fmaxf(t, __shfl_xor_sync(0xFFFFFFFFu, t, o));
        if (threadIdx.x == 0) sm[0] = t;
    }
    __syncthreads();
    float sx = sm[0] / 127.0f;
    if (sx == 0.f) sx = 1.0f;
    if (threadIdx.x == 0) g_sx[row] = sx;

    uint4 o1, o2;
    float q[16];
#pragma unroll
    for (int i = 0; i < 4; i++) {
        q[4 * i + 0] = fminf(fmaxf(rintf(v[i].x / sx), -127.f), 127.f);
        q[4 * i + 1] = fminf(fmaxf(rintf(v[i].y / sx), -127.f), 127.f);
        q[4 * i + 2] = fminf(fmaxf(rintf(v[i].z / sx), -127.f), 127.f);
        q[4 * i + 3] = fminf(fmaxf(rintf(v[i].w / sx), -127.f), 127.f);
    }
    o1.x = pack_bf16x2(q[0], q[1]);  o1.y = pack_bf16x2(q[2], q[3]);
    o1.z = pack_bf16x2(q[4], q[5]);  o1.w = pack_bf16x2(q[6], q[7]);
    o2.x = pack_bf16x2(q[8], q[9]);  o2.y = pack_bf16x2(q[10], q[11]);
    o2.z = pack_bf16x2(q[12], q[13]); o2.w = pack_bf16x2(q[14], q[15]);
    uint4* outp = reinterpret_cast<uint4*>(g_xq + (size_t)row * K_DIM);
    outp[threadIdx.x * 2 + 0] = o1;
    outp[threadIdx.x * 2 + 1] = o2;
}

// ------------------------- kernel 2: weights int32 -> bf16 ---------------
__global__ void __launch_bounds__(256) quant_w_kernel(const int* __restrict__ w) {
    const long total8 = (long)N_DIM * K_DIM / 8;     // uint4 (8 bf16) outputs
    long gid = blockIdx.x * 256L + threadIdx.x;
    long stride = gridDim.x * 256L;
    const int4* wv = reinterpret_cast<const int4*>(w);
    uint4* out = reinterpret_cast<uint4*>(g_wq);
    for (; gid < total8; gid += stride) {
        int4 a = wv[gid * 2 + 0];
        int4 b = wv[gid * 2 + 1];
        uint4 o;
        o.x = pack_bf16x2((float)a.x, (float)a.y);
        o.y = pack_bf16x2((float)a.z, (float)a.w);
        o.z = pack_bf16x2((float)b.x, (float)b.y);
        o.w = pack_bf16x2((float)b.z, (float)b.w);
        out[gid] = o;
    }
}

// ------------------------- kernel 3: bf16 HMMA GEMM ----------------------
// 128x256 CTA tile, 512 threads = 16 warps (4 M x 4 N), 32x64 warp tiles,
// 4-stage cp.async pipeline (wait_group 2), ldmatrix + mma.m16n8k16.bf16
__device__ __forceinline__ void load_stage(uint32_t sbase, int m0, int n0,
                                           int kblk, int tid) {
    const int kb = kblk * 128;          // bytes along K (BK bf16 * 2)
#pragma unroll
    for (int i = 0; i < 2; i++) {       // A: 128 rows x 128 B = 1024 chunks
        int id = tid + i * GTHREADS;
        int r = id >> 3, c = id & 7;
        const char* g = reinterpret_cast<const char*>(g_xq + (size_t)(m0 + r) * K_DIM) + kb + c * 16;
        cp_async16(sbase + swz128((uint32_t)(r * 128 + c * 16)), g);
    }
#pragma unroll
    for (int i = 0; i < 4; i++) {       // B: 256 rows x 128 B = 2048 chunks
        int id = tid + i * GTHREADS;
        int r = id >> 3, c = id & 7;
        const char* g = reinterpret_cast<const char*>(g_wq + (size_t)(n0 + r) * K_DIM) + kb + c * 16;
        cp_async16(sbase + A_SMEM + swz128((uint32_t)(r * 128 + c * 16)), g);
    }
}

__global__ void __launch_bounds__(GTHREADS, 1) gemm_kernel(float* __restrict__ out,
                                                           const float* __restrict__ scale,
                                                           const float* __restrict__ bias) {
    extern __shared__ char smem[];
    const uint32_t sb = smem_u32(smem);
    const int tid = threadIdx.x;
    const int wid = tid >> 5;           // 0..15
    const int lane = tid & 31;
    const int n0 = blockIdx.x * BN;
    const int m0 = blockIdx.y * BM;
    const int wm = wid >> 2;            // 0..3 -> 32-row slice
    const int wn = wid & 3;             // 0..3 -> 64-col slice

    // ldmatrix per-lane addressing (q = matrix index 0..3, rw = row in 8x8)
    const int q = lane >> 3;
    const int rw = lane & 7;
    const uint32_t mask = (uint32_t)rw << 4;      // SW128 swizzle for this row
    const int kbA = (q >> 1) * 16;      // A mats: {m0-7/k0-7, m8-15/k0-7, m0-7/k8-15, m8-15/k8-15}
    const int kbB = (q & 1) * 16;       // B mats: {n0-7/k0-7, n0-7/k8-15, n8-15/k0-7, n8-15/k8-15}
    uint32_t rowA[2], rowB[4];
#pragma unroll
    for (int mi = 0; mi < 2; mi++)
        rowA[mi] = (uint32_t)((wm * 32 + mi * 16 + (q & 1) * 8 + rw) * 128);
#pragma unroll
    for (int nj = 0; nj < 4; nj++)
        rowB[nj] = (uint32_t)(A_SMEM + (wn * 64 + nj * 16 + (q >> 1) * 8 + rw) * 128);

    float acc[2][8][4];
#pragma unroll
    for (int mi = 0; mi < 2; mi++)
#pragma unroll
        for (int nj = 0; nj < 8; nj++)
#pragma unroll
            for (int t = 0; t < 4; t++) acc[mi][nj][t] = 0.f;

    // prologue: stages 0..2 in flight
    load_stage(sb + 0 * STAGE_BYTES, m0, n0, 0, tid); cp_commit();
    load_stage(sb + 1 * STAGE_BYTES, m0, n0, 1, tid); cp_commit();
    load_stage(sb + 2 * STAGE_BYTES, m0, n0, 2, tid); cp_commit();

    for (int k = 0; k < KSTEPS; k++) {
        cp_wait2();                      // stage k complete (oldest pending)
        __syncthreads();                 // all warps past compute of k-1
        if (k + 3 < KSTEPS)
            load_stage(sb + ((k + 3) % STAGES) * STAGE_BYTES, m0, n0, k + 3, tid);
        cp_commit();                     // unconditional: keeps group accounting

        const uint32_t stg = sb + (k % STAGES) * STAGE_BYTES;
#pragma unroll
        for (int ks = 0; ks < 4; ks++) {          // 4 x k16 per 64-elem stage
            const uint32_t koffA = (uint32_t)((ks * 32 + kbA) ^ (int)mask);
            const uint32_t koffB = (uint32_t)((ks * 32 + kbB) ^ (int)mask);
            uint32_t a[2][4], b[4][4];
#pragma unroll
            for (int mi = 0; mi < 2; mi++) ldm_x4(a[mi], stg + rowA[mi] + koffA);
#pragma unroll
            for (int nj = 0; nj < 4; nj++) ldm_x4(b[nj], stg + rowB[nj] + koffB);
#pragma unroll
            for (int mi = 0; mi < 2; mi++) {
#pragma unroll
                for (int nj = 0; nj < 4; nj++) {
                    mma_bf16(acc[mi][2 * nj + 0], a[mi], b[nj][0], b[nj][1]);
                    mma_bf16(acc[mi][2 * nj + 1], a[mi], b[nj][2], b[nj][3]);
                }
            }
        }
    }

    // ------------- epilogue: dequant + bias, float2 stores ---------------
    const int nbase = n0 + wn * 64;
#pragma unroll
    for (int mi = 0; mi < 2; mi++) {
        const int mlo = m0 + wm * 32 + mi * 16 + (lane >> 2);
        const int mhi = mlo + 8;
        const float slo = g_sx[mlo];
        const float shi = g_sx[mhi];
        float* orow_lo = out + (size_t)mlo * N_DIM + nbase;
        float* orow_hi = out + (size_t)mhi * N_DIM + nbase;
#pragma unroll
        for (int nj = 0; nj < 8; nj++) {
            const int n = nj * 8 + 2 * (lane & 3);
            const float2 sc = *reinterpret_cast<const float2*>(scale + nbase + n);
            const float2 bi = *reinterpret_cast<const float2*>(bias + nbase + n);
            const float* c = acc[mi][nj];
            float2 vlo, vhi;
            vlo.x = fmaf(c[0] * slo, sc.x, bi.x);
            vlo.y = fmaf(c[1] * slo, sc.y, bi.y);
            vhi.x = fmaf(c[2] * shi, sc.x, bi.x);
            vhi.y = fmaf(c[3] * shi, sc.y, bi.y);
            *reinterpret_cast<float2*>(orow_lo + n) = vlo;
            *reinterpret_cast<float2*>(orow_hi + n) = vhi;
        }
    }
}

// ------------------------- launch ---------------------------------------
extern "C" void kernel_launch(void* const* d_in, const int* in_sizes, int n_in,
                              void* d_out, int out_size) {
    const float* x = (const float*)d_in[0];
    const int* w = (const int*)d_in[1];
    const float* scale = (const float*)d_in[2];
    const float* bias = (const float*)d_in[3];
    float* out = (float*)d_out;

    const int M = in_sizes[0] / K_DIM;   // 8192

    static int smem_set = 0;
    if (!smem_set) {
        cudaFuncSetAttribute(gemm_kernel, cudaFuncAttributeMaxDynamicSharedMemorySize,
                             GEMM_SMEM);
        smem_set = 1;
    }

    quant_x_kernel<<<M, 256>>>(x);
    quant_w_kernel<<<16384, 256>>>(w);
    gemm_kernel<<<dim3(N_DIM / BN, M / BM), GTHREADS, GEMM_SMEM>>>(out, scale, bias);
}

// round 6
// speedup vs baseline: 3.1357x; 1.0778x over previous
#include <cuda_runtime.h>
#include <cuda_bf16.h>
#include <stdint.h>

#define K_DIM 4096
#define N_DIM 16384
#define M_MAX 8192

#define BM 128
#define BN 256
#define BK 64                        // bf16 elems of K per stage (128 bytes)
#define STAGES 4
#define KSTEPS (K_DIM / BK)          // 64
#define A_SMEM (BM * 128)            // 16384 bytes
#define B_SMEM (BN * 128)            // 32768 bytes
#define STAGE_BYTES (A_SMEM + B_SMEM)    // 49152
#define GEMM_SMEM (STAGES * STAGE_BYTES) // 196608
#define GTHREADS 256

// ------------------------- scratch (device globals; no runtime alloc) ---
__device__ __nv_bfloat16 g_xq[(size_t)M_MAX * K_DIM];   // 64 MB bf16 x
__device__ __nv_bfloat16 g_wq[(size_t)N_DIM * K_DIM];   // 128 MB bf16 w
__device__ float g_sx[M_MAX];

// ------------------------- helpers --------------------------------------
__device__ __forceinline__ uint32_t smem_u32(const void* p) {
    uint32_t a;
    asm("{ .reg .u64 t; cvta.to.shared.u64 t, %1; cvt.u32.u64 %0, t; }"
        : "=r"(a) : "l"(p));
    return a;
}
__device__ __forceinline__ uint32_t swz128(uint32_t b) { return b ^ ((b >> 3) & 0x70); }

__device__ __forceinline__ void cp_async16(uint32_t s, const void* g) {
    asm volatile("cp.async.cg.shared.global [%0], [%1], 16;" :: "r"(s), "l"(g));
}
__device__ __forceinline__ void cp_commit() {
    asm volatile("cp.async.commit_group;" ::: "memory");
}
__device__ __forceinline__ void cp_wait1() {
    asm volatile("cp.async.wait_group 1;" ::: "memory");
}

__device__ __forceinline__ void ldm_x4(uint32_t* r, uint32_t addr) {
    asm volatile("ldmatrix.sync.aligned.m8n8.x4.shared.b16 {%0,%1,%2,%3}, [%4];"
        : "=r"(r[0]), "=r"(r[1]), "=r"(r[2]), "=r"(r[3]) : "r"(addr));
}

// bf16 HMMA: D(f32) += A(bf16) * B(bf16), m16n8k16
__device__ __forceinline__ void mma_bf16(float* c, const uint32_t* a, uint32_t b0, uint32_t b1) {
    asm volatile("mma.sync.aligned.m16n8k16.row.col.f32.bf16.bf16.f32 "
        "{%0,%1,%2,%3}, {%4,%5,%6,%7}, {%8,%9}, {%0,%1,%2,%3};"
        : "+f"(c[0]), "+f"(c[1]), "+f"(c[2]), "+f"(c[3])
        : "r"(a[0]), "r"(a[1]), "r"(a[2]), "r"(a[3]), "r"(b0), "r"(b1));
}

__device__ __forceinline__ uint32_t pack_bf16x2(float a, float b) {
    __nv_bfloat162 h = __floats2bfloat162_rn(a, b);
    return *reinterpret_cast<uint32_t*>(&h);
}

// ------------------------- kernel 1: quantize x -> bf16 ------------------
__global__ void __launch_bounds__(256) quant_x_kernel(const float* __restrict__ x) {
    const int row = blockIdx.x;
    const float4* xv = reinterpret_cast<const float4*>(x + (size_t)row * K_DIM);

    float4 v[4];
    float m = 0.f;
#pragma unroll
    for (int i = 0; i < 4; i++) {
        v[i] = xv[threadIdx.x * 4 + i];
        m = fmaxf(m, fmaxf(fmaxf(fabsf(v[i].x), fabsf(v[i].y)),
                           fmaxf(fabsf(v[i].z), fabsf(v[i].w))));
    }
#pragma unroll
    for (int o = 16; o; o >>= 1) m = fmaxf(m, __shfl_xor_sync(0xFFFFFFFFu, m, o));

    __shared__ float sm[8];
    if ((threadIdx.x & 31) == 0) sm[threadIdx.x >> 5] = m;
    __syncthreads();
    if (threadIdx.x < 32) {
        float t = (threadIdx.x < 8) ? sm[threadIdx.x] : 0.f;
#pragma unroll
        for (int o = 4; o; o >>= 1) t = fmaxf(t, __shfl_xor_sync(0xFFFFFFFFu, t, o));
        if (threadIdx.x == 0) sm[0] = t;
    }
    __syncthreads();
    float sx = sm[0] / 127.0f;
    if (sx == 0.f) sx = 1.0f;
    if (threadIdx.x == 0) g_sx[row] = sx;

    uint4 o1, o2;
    float q[16];
#pragma unroll
    for (int i = 0; i < 4; i++) {
        q[4 * i + 0] = fminf(fmaxf(rintf(v[i].x / sx), -127.f), 127.f);
        q[4 * i + 1] = fminf(fmaxf(rintf(v[i].y / sx), -127.f), 127.f);
        q[4 * i + 2] = fminf(fmaxf(rintf(v[i].z / sx), -127.f), 127.f);
        q[4 * i + 3] = fminf(fmaxf(rintf(v[i].w / sx), -127.f), 127.f);
    }
    o1.x = pack_bf16x2(q[0], q[1]);  o1.y = pack_bf16x2(q[2], q[3]);
    o1.z = pack_bf16x2(q[4], q[5]);  o1.w = pack_bf16x2(q[6], q[7]);
    o2.x = pack_bf16x2(q[8], q[9]);  o2.y = pack_bf16x2(q[10], q[11]);
    o2.z = pack_bf16x2(q[12], q[13]); o2.w = pack_bf16x2(q[14], q[15]);
    uint4* outp = reinterpret_cast<uint4*>(g_xq + (size_t)row * K_DIM);
    outp[threadIdx.x * 2 + 0] = o1;
    outp[threadIdx.x * 2 + 1] = o2;
}

// ------------------------- kernel 2: weights int32 -> bf16 ---------------
__global__ void __launch_bounds__(256) quant_w_kernel(const int* __restrict__ w) {
    const long total8 = (long)N_DIM * K_DIM / 8;
    long gid = blockIdx.x * 256L + threadIdx.x;
    long stride = gridDim.x * 256L;
    const int4* wv = reinterpret_cast<const int4*>(w);
    uint4* out = reinterpret_cast<uint4*>(g_wq);
    for (; gid < total8; gid += stride) {
        int4 a = wv[gid * 2 + 0];
        int4 b = wv[gid * 2 + 1];
        uint4 o;
        o.x = pack_bf16x2((float)a.x, (float)a.y);
        o.y = pack_bf16x2((float)a.z, (float)a.w);
        o.z = pack_bf16x2((float)b.x, (float)b.y);
        o.w = pack_bf16x2((float)b.z, (float)b.w);
        out[gid] = o;
    }
}

// ------------------------- kernel 3: bf16 HMMA GEMM ----------------------
// 128x256 CTA tile, 8 warps (2 M x 4 N), 64x64 warp tiles,
// 4-stage cp.async pipeline (wait_group 1), fragment double-buffering.
__global__ void __launch_bounds__(GTHREADS, 1) gemm_kernel(float* __restrict__ out,
                                                           const float* __restrict__ scale,
                                                           const float* __restrict__ bias) {
    extern __shared__ char smem[];
    const uint32_t sb = smem_u32(smem);
    const int tid = threadIdx.x;
    const int wid = tid >> 5;
    const int lane = tid & 31;
    const int n0 = blockIdx.x * BN;
    const int m0 = blockIdx.y * BM;
    const int wm = wid >> 2;            // 0..1
    const int wn = wid & 3;             // 0..3

    // --- cp.async addressing: one base pointer + constant strides --------
    const int r0 = tid >> 3;            // 0..31
    const int c0 = tid & 7;             // 0..7 (16B chunk in row)
    const char* baseA = reinterpret_cast<const char*>(g_xq)
                        + (size_t)(m0 + r0) * (K_DIM * 2) + c0 * 16;
    const char* baseB = reinterpret_cast<const char*>(g_wq)
                        + (size_t)(n0 + r0) * (K_DIM * 2) + c0 * 16;
    const uint32_t sA0 = sb + swz128((uint32_t)(r0 * 128 + c0 * 16));
    const uint32_t sB0 = sA0 + A_SMEM;  // swizzle unaffected by +16384/+4096 deltas

    // --- ldmatrix per-lane addressing -------------------------------------
    const int q = lane >> 3;
    const int rw = lane & 7;
    const uint32_t mask = (uint32_t)rw << 4;
    const int kbA = (q >> 1) * 16;
    const int kbB = (q & 1) * 16;
    uint32_t rowA[4], rowB[4];
#pragma unroll
    for (int mi = 0; mi < 4; mi++)
        rowA[mi] = (uint32_t)((wm * 64 + mi * 16 + (q & 1) * 8 + rw) * 128);
#pragma unroll
    for (int nj = 0; nj < 4; nj++)
        rowB[nj] = (uint32_t)(A_SMEM + (wn * 64 + nj * 16 + (q >> 1) * 8 + rw) * 128);

    float acc[4][8][4];
#pragma unroll
    for (int mi = 0; mi < 4; mi++)
#pragma unroll
        for (int nj = 0; nj < 8; nj++)
#pragma unroll
            for (int t = 0; t < 4; t++) acc[mi][nj][t] = 0.f;

    // --- stage loader ------------------------------------------------------
    auto load_stage = [&](int slot, int kblk) {
        const uint32_t soff = (uint32_t)slot * STAGE_BYTES;
        const int kb = kblk * 128;
#pragma unroll
        for (int i = 0; i < 4; i++)     // A: 128 rows, 32 rows per step
            cp_async16(sA0 + soff + i * 4096u, baseA + (size_t)i * 262144 + kb);
#pragma unroll
        for (int i = 0; i < 8; i++)     // B: 256 rows
            cp_async16(sB0 + soff + i * 4096u, baseB + (size_t)i * 262144 + kb);
    };

    // --- fragment loader ----------------------------------------------------
    auto load_frags = [&](uint32_t a[4][4], uint32_t b[4][4], uint32_t stg, int ks) {
        const uint32_t koffA = (uint32_t)((ks * 32 + kbA) ^ (int)mask);
        const uint32_t koffB = (uint32_t)((ks * 32 + kbB) ^ (int)mask);
#pragma unroll
        for (int mi = 0; mi < 4; mi++) ldm_x4(a[mi], stg + rowA[mi] + koffA);
#pragma unroll
        for (int nj = 0; nj < 4; nj++) ldm_x4(b[nj], stg + rowB[nj] + koffB);
    };

    // prologue: stages 0..2 in flight
    load_stage(0, 0); cp_commit();
    load_stage(1, 1); cp_commit();
    load_stage(2, 2); cp_commit();

    uint32_t af[2][4][4], bf[2][4][4];

    for (int k = 0; k < KSTEPS; k++) {
        cp_wait1();                      // stages k AND k+1 complete
        __syncthreads();                 // writes visible; stage k-1 fully consumed
        if (k + 3 < KSTEPS)
            load_stage((k + 3) % STAGES, k + 3);
        cp_commit();                     // unconditional: group accounting

        const uint32_t stg  = sb + (uint32_t)(k % STAGES) * STAGE_BYTES;
        const uint32_t stgn = sb + (uint32_t)((k + 1) % STAGES) * STAGE_BYTES;

        if (k == 0) load_frags(af[0], bf[0], stg, 0);

#pragma unroll
        for (int ks = 0; ks < 4; ks++) {
            const int pb = ks & 1;
            const int nb = pb ^ 1;
            // prefetch next fragments (next ks, or next stage's ks=0)
            if (ks < 3) load_frags(af[nb], bf[nb], stg, ks + 1);
            else        load_frags(af[nb], bf[nb], stgn, 0);
            // compute on current fragments
#pragma unroll
            for (int mi = 0; mi < 4; mi++) {
#pragma unroll
                for (int nj = 0; nj < 4; nj++) {
                    mma_bf16(acc[mi][2 * nj + 0], af[pb][mi], bf[pb][nj][0], bf[pb][nj][1]);
                    mma_bf16(acc[mi][2 * nj + 1], af[pb][mi], bf[pb][nj][2], bf[pb][nj][3]);
                }
            }
        }
    }

    // ------------- epilogue: dequant + bias, float2 stores ---------------
    const int nbase = n0 + wn * 64;
#pragma unroll
    for (int mi = 0; mi < 4; mi++) {
        const int mlo = m0 + wm * 64 + mi * 16 + (lane >> 2);
        const int mhi = mlo + 8;
        const float slo = g_sx[mlo];
        const float shi = g_sx[mhi];
        float* orow_lo = out + (size_t)mlo * N_DIM + nbase;
        float* orow_hi = out + (size_t)mhi * N_DIM + nbase;
#pragma unroll
        for (int nj = 0; nj < 8; nj++) {
            const int n = nj * 8 + 2 * (lane & 3);
            const float2 sc = *reinterpret_cast<const float2*>(scale + nbase + n);
            const float2 bi = *reinterpret_cast<const float2*>(bias + nbase + n);
            const float* c = acc[mi][nj];
            float2 vlo, vhi;
            vlo.x = fmaf(c[0] * slo, sc.x, bi.x);
            vlo.y = fmaf(c[1] * slo, sc.y, bi.y);
            vhi.x = fmaf(c[2] * shi, sc.x, bi.x);
            vhi.y = fmaf(c[3] * shi, sc.y, bi.y);
            *reinterpret_cast<float2*>(orow_lo + n) = vlo;
            *reinterpret_cast<float2*>(orow_hi + n) = vhi;
        }
    }
}

// ------------------------- launch ---------------------------------------
extern "C" void kernel_launch(void* const* d_in, const int* in_sizes, int n_in,
                              void* d_out, int out_size) {
    const float* x = (const float*)d_in[0];
    const int* w = (const int*)d_in[1];
    const float* scale = (const float*)d_in[2];
    const float* bias = (const float*)d_in[3];
    float* out = (float*)d_out;

    const int M = in_sizes[0] / K_DIM;   // 8192

    static int smem_set = 0;
    if (!smem_set) {
        cudaFuncSetAttribute(gemm_kernel, cudaFuncAttributeMaxDynamicSharedMemorySize,
                             GEMM_SMEM);
        smem_set = 1;
    }

    quant_x_kernel<<<M, 256>>>(x);
    quant_w_kernel<<<16384, 256>>>(w);
    gemm_kernel<<<dim3(N_DIM / BN, M / BM), GTHREADS, GEMM_SMEM>>>(out, scale, bias);
}

// round 7
// speedup vs baseline: 3.1384x; 1.0009x over previous
#include <cuda_runtime.h>
#include <cuda_bf16.h>
#include <stdint.h>

#define K_DIM 4096
#define N_DIM 16384
#define M_MAX 8192

#define BM 128
#define BN 256
#define BK 64                        // bf16 elems of K per stage (128 bytes)
#define STAGES 4
#define KSTEPS (K_DIM / BK)          // 64
#define A_SMEM (BM * 128)            // 16384 bytes
#define B_SMEM (BN * 128)            // 32768 bytes
#define STAGE_BYTES (A_SMEM + B_SMEM)    // 49152
#define GEMM_SMEM (STAGES * STAGE_BYTES) // 196608
#define GTHREADS 256

#define TILES_M (M_MAX / BM)         // 64
#define TILES_N (N_DIM / BN)         // 64
#define RASTER_GROUP 8               // n-tiles per raster column group

// ------------------------- scratch (device globals; no runtime alloc) ---
__device__ __nv_bfloat16 g_xq[(size_t)M_MAX * K_DIM];   // 64 MB bf16 x
__device__ __nv_bfloat16 g_wq[(size_t)N_DIM * K_DIM];   // 128 MB bf16 w
__device__ float g_sx[M_MAX];

// ------------------------- helpers --------------------------------------
__device__ __forceinline__ uint32_t smem_u32(const void* p) {
    uint32_t a;
    asm("{ .reg .u64 t; cvta.to.shared.u64 t, %1; cvt.u32.u64 %0, t; }"
        : "=r"(a) : "l"(p));
    return a;
}
__device__ __forceinline__ uint32_t swz128(uint32_t b) { return b ^ ((b >> 3) & 0x70); }

__device__ __forceinline__ void cp_async16(uint32_t s, const void* g) {
    asm volatile("cp.async.cg.shared.global [%0], [%1], 16;" :: "r"(s), "l"(g));
}
__device__ __forceinline__ void cp_commit() {
    asm volatile("cp.async.commit_group;" ::: "memory");
}
__device__ __forceinline__ void cp_wait1() {
    asm volatile("cp.async.wait_group 1;" ::: "memory");
}

__device__ __forceinline__ void ldm_x4(uint32_t* r, uint32_t addr) {
    asm volatile("ldmatrix.sync.aligned.m8n8.x4.shared.b16 {%0,%1,%2,%3}, [%4];"
        : "=r"(r[0]), "=r"(r[1]), "=r"(r[2]), "=r"(r[3]) : "r"(addr));
}

// bf16 HMMA: D(f32) += A(bf16) * B(bf16), m16n8k16
__device__ __forceinline__ void mma_bf16(float* c, const uint32_t* a, uint32_t b0, uint32_t b1) {
    asm volatile("mma.sync.aligned.m16n8k16.row.col.f32.bf16.bf16.f32 "
        "{%0,%1,%2,%3}, {%4,%5,%6,%7}, {%8,%9}, {%0,%1,%2,%3};"
        : "+f"(c[0]), "+f"(c[1]), "+f"(c[2]), "+f"(c[3])
        : "r"(a[0]), "r"(a[1]), "r"(a[2]), "r"(a[3]), "r"(b0), "r"(b1));
}

__device__ __forceinline__ uint32_t pack_bf16x2(float a, float b) {
    __nv_bfloat162 h = __floats2bfloat162_rn(a, b);
    return *reinterpret_cast<uint32_t*>(&h);
}

// ------------------------- kernel 1: quantize x -> bf16 ------------------
__global__ void __launch_bounds__(256) quant_x_kernel(const float* __restrict__ x) {
    const int row = blockIdx.x;
    const float4* xv = reinterpret_cast<const float4*>(x + (size_t)row * K_DIM);

    float4 v[4];
    float m = 0.f;
#pragma unroll
    for (int i = 0; i < 4; i++) {
        v[i] = xv[threadIdx.x * 4 + i];
        m = fmaxf(m, fmaxf(fmaxf(fabsf(v[i].x), fabsf(v[i].y)),
                           fmaxf(fabsf(v[i].z), fabsf(v[i].w))));
    }
#pragma unroll
    for (int o = 16; o; o >>= 1) m = fmaxf(m, __shfl_xor_sync(0xFFFFFFFFu, m, o));

    __shared__ float sm[8];
    if ((threadIdx.x & 31) == 0) sm[threadIdx.x >> 5] = m;
    __syncthreads();
    if (threadIdx.x < 32) {
        float t = (threadIdx.x < 8) ? sm[threadIdx.x] : 0.f;
#pragma unroll
        for (int o = 4; o; o >>= 1) t = fmaxf(t, __shfl_xor_sync(0xFFFFFFFFu, t, o));
        if (threadIdx.x == 0) sm[0] = t;
    }
    __syncthreads();
    float sx = sm[0] / 127.0f;
    if (sx == 0.f) sx = 1.0f;
    if (threadIdx.x == 0) g_sx[row] = sx;

    uint4 o1, o2;
    float q[16];
#pragma unroll
    for (int i = 0; i < 4; i++) {
        q[4 * i + 0] = fminf(fmaxf(rintf(v[i].x / sx), -127.f), 127.f);
        q[4 * i + 1] = fminf(fmaxf(rintf(v[i].y / sx), -127.f), 127.f);
        q[4 * i + 2] = fminf(fmaxf(rintf(v[i].z / sx), -127.f), 127.f);
        q[4 * i + 3] = fminf(fmaxf(rintf(v[i].w / sx), -127.f), 127.f);
    }
    o1.x = pack_bf16x2(q[0], q[1]);  o1.y = pack_bf16x2(q[2], q[3]);
    o1.z = pack_bf16x2(q[4], q[5]);  o1.w = pack_bf16x2(q[6], q[7]);
    o2.x = pack_bf16x2(q[8], q[9]);  o2.y = pack_bf16x2(q[10], q[11]);
    o2.z = pack_bf16x2(q[12], q[13]); o2.w = pack_bf16x2(q[14], q[15]);
    uint4* outp = reinterpret_cast<uint4*>(g_xq + (size_t)row * K_DIM);
    outp[threadIdx.x * 2 + 0] = o1;
    outp[threadIdx.x * 2 + 1] = o2;
}

// ------------------------- kernel 2: weights int32 -> bf16 ---------------
__global__ void __launch_bounds__(256) quant_w_kernel(const int* __restrict__ w) {
    const long total8 = (long)N_DIM * K_DIM / 8;
    long gid = blockIdx.x * 256L + threadIdx.x;
    long stride = gridDim.x * 256L;
    const int4* wv = reinterpret_cast<const int4*>(w);
    uint4* out = reinterpret_cast<uint4*>(g_wq);
    for (; gid < total8; gid += stride) {
        int4 a = wv[gid * 2 + 0];
        int4 b = wv[gid * 2 + 1];
        uint4 o;
        o.x = pack_bf16x2((float)a.x, (float)a.y);
        o.y = pack_bf16x2((float)a.z, (float)a.w);
        o.z = pack_bf16x2((float)b.x, (float)b.y);
        o.w = pack_bf16x2((float)b.z, (float)b.w);
        out[gid] = o;
    }
}

// ------------------------- kernel 3: bf16 HMMA GEMM ----------------------
// 128x256 CTA tile, 8 warps (2 M x 4 N), 64x64 warp tiles,
// 4-stage cp.async pipeline (wait_group 1), fragment double-buffering,
// L2-friendly CTA rasterization (8 n-tiles per column group).
__global__ void __launch_bounds__(GTHREADS, 1) gemm_kernel(float* __restrict__ out,
                                                           const float* __restrict__ scale,
                                                           const float* __restrict__ bias) {
    extern __shared__ char smem[];
    const uint32_t sb = smem_u32(smem);
    const int tid = threadIdx.x;
    const int wid = tid >> 5;
    const int lane = tid & 31;

    // ---- L2-friendly rasterization: wave covers 8 n-tiles x ~18 m-tiles --
    const int bid = blockIdx.x;
    const int group = bid / (RASTER_GROUP * TILES_M);
    const int rem = bid % (RASTER_GROUP * TILES_M);
    const int mt = rem / RASTER_GROUP;
    const int nt = group * RASTER_GROUP + (rem % RASTER_GROUP);
    const int n0 = nt * BN;
    const int m0 = mt * BM;

    const int wm = wid >> 2;            // 0..1
    const int wn = wid & 3;             // 0..3

    // --- cp.async addressing: one base pointer + constant strides --------
    const int r0 = tid >> 3;            // 0..31
    const int c0 = tid & 7;             // 0..7 (16B chunk in row)
    const char* baseA = reinterpret_cast<const char*>(g_xq)
                        + (size_t)(m0 + r0) * (K_DIM * 2) + c0 * 16;
    const char* baseB = reinterpret_cast<const char*>(g_wq)
                        + (size_t)(n0 + r0) * (K_DIM * 2) + c0 * 16;
    const uint32_t sA0 = sb + swz128((uint32_t)(r0 * 128 + c0 * 16));
    const uint32_t sB0 = sA0 + A_SMEM;

    // --- ldmatrix per-lane addressing -------------------------------------
    const int q = lane >> 3;
    const int rw = lane & 7;
    const uint32_t mask = (uint32_t)rw << 4;
    const int kbA = (q >> 1) * 16;
    const int kbB = (q & 1) * 16;
    uint32_t rowA[4], rowB[4];
#pragma unroll
    for (int mi = 0; mi < 4; mi++)
        rowA[mi] = (uint32_t)((wm * 64 + mi * 16 + (q & 1) * 8 + rw) * 128);
#pragma unroll
    for (int nj = 0; nj < 4; nj++)
        rowB[nj] = (uint32_t)(A_SMEM + (wn * 64 + nj * 16 + (q >> 1) * 8 + rw) * 128);

    float acc[4][8][4];
#pragma unroll
    for (int mi = 0; mi < 4; mi++)
#pragma unroll
        for (int nj = 0; nj < 8; nj++)
#pragma unroll
            for (int t = 0; t < 4; t++) acc[mi][nj][t] = 0.f;

    // --- stage loader ------------------------------------------------------
    auto load_stage = [&](int slot, int kblk) {
        const uint32_t soff = (uint32_t)slot * STAGE_BYTES;
        const int kb = kblk * 128;
#pragma unroll
        for (int i = 0; i < 4; i++)     // A: 128 rows, 32 rows per step
            cp_async16(sA0 + soff + i * 4096u, baseA + (size_t)i * 262144 + kb);
#pragma unroll
        for (int i = 0; i < 8; i++)     // B: 256 rows
            cp_async16(sB0 + soff + i * 4096u, baseB + (size_t)i * 262144 + kb);
    };

    // --- fragment loader ----------------------------------------------------
    auto load_frags = [&](uint32_t a[4][4], uint32_t b[4][4], uint32_t stg, int ks) {
        const uint32_t koffA = (uint32_t)((ks * 32 + kbA) ^ (int)mask);
        const uint32_t koffB = (uint32_t)((ks * 32 + kbB) ^ (int)mask);
#pragma unroll
        for (int mi = 0; mi < 4; mi++) ldm_x4(a[mi], stg + rowA[mi] + koffA);
#pragma unroll
        for (int nj = 0; nj < 4; nj++) ldm_x4(b[nj], stg + rowB[nj] + koffB);
    };

    // prologue: stages 0..2 in flight
    load_stage(0, 0); cp_commit();
    load_stage(1, 1); cp_commit();
    load_stage(2, 2); cp_commit();

    uint32_t af[2][4][4], bf[2][4][4];

    for (int k = 0; k < KSTEPS; k++) {
        cp_wait1();                      // stages k AND k+1 complete
        __syncthreads();                 // writes visible; stage k-1 fully consumed
        if (k + 3 < KSTEPS)
            load_stage((k + 3) % STAGES, k + 3);
        cp_commit();                     // unconditional: group accounting

        const uint32_t stg  = sb + (uint32_t)(k % STAGES) * STAGE_BYTES;
        const uint32_t stgn = sb + (uint32_t)((k + 1) % STAGES) * STAGE_BYTES;

        if (k == 0) load_frags(af[0], bf[0], stg, 0);

#pragma unroll
        for (int ks = 0; ks < 4; ks++) {
            const int pb = ks & 1;
            const int nb = pb ^ 1;
            if (ks < 3) load_frags(af[nb], bf[nb], stg, ks + 1);
            else        load_frags(af[nb], bf[nb], stgn, 0);
#pragma unroll
            for (int mi = 0; mi < 4; mi++) {
#pragma unroll
                for (int nj = 0; nj < 4; nj++) {
                    mma_bf16(acc[mi][2 * nj + 0], af[pb][mi], bf[pb][nj][0], bf[pb][nj][1]);
                    mma_bf16(acc[mi][2 * nj + 1], af[pb][mi], bf[pb][nj][2], bf[pb][nj][3]);
                }
            }
        }
    }

    // ------------- epilogue: dequant + bias, float2 stores ---------------
    const int nbase = n0 + wn * 64;
#pragma unroll
    for (int mi = 0; mi < 4; mi++) {
        const int mlo = m0 + wm * 64 + mi * 16 + (lane >> 2);
        const int mhi = mlo + 8;
        const float slo = g_sx[mlo];
        const float shi = g_sx[mhi];
        float* orow_lo = out + (size_t)mlo * N_DIM + nbase;
        float* orow_hi = out + (size_t)mhi * N_DIM + nbase;
#pragma unroll
        for (int nj = 0; nj < 8; nj++) {
            const int n = nj * 8 + 2 * (lane & 3);
            const float2 sc = *reinterpret_cast<const float2*>(scale + nbase + n);
            const float2 bi = *reinterpret_cast<const float2*>(bias + nbase + n);
            const float* c = acc[mi][nj];
            float2 vlo, vhi;
            vlo.x = fmaf(c[0] * slo, sc.x, bi.x);
            vlo.y = fmaf(c[1] * slo, sc.y, bi.y);
            vhi.x = fmaf(c[2] * shi, sc.x, bi.x);
            vhi.y = fmaf(c[3] * shi, sc.y, bi.y);
            *reinterpret_cast<float2*>(orow_lo + n) = vlo;
            *reinterpret_cast<float2*>(orow_hi + n) = vhi;
        }
    }
}

// ------------------------- launch ---------------------------------------
extern "C" void kernel_launch(void* const* d_in, const int* in_sizes, int n_in,
                              void* d_out, int out_size) {
    const float* x = (const float*)d_in[0];
    const int* w = (const int*)d_in[1];
    const float* scale = (const float*)d_in[2];
    const float* bias = (const float*)d_in[3];
    float* out = (float*)d_out;

    const int M = in_sizes[0] / K_DIM;   // 8192

    static int smem_set = 0;
    if (!smem_set) {
        cudaFuncSetAttribute(gemm_kernel, cudaFuncAttributeMaxDynamicSharedMemorySize,
                             GEMM_SMEM);
        smem_set = 1;
    }

    quant_x_kernel<<<M, 256>>>(x);
    quant_w_kernel<<<16384, 256>>>(w);
    gemm_kernel<<<TILES_M * TILES_N, GTHREADS, GEMM_SMEM>>>(out, scale, bias);
}

// round 8
// speedup vs baseline: 3.1957x; 1.0183x over previous
#include <cuda_runtime.h>
#include <cuda_bf16.h>
#include <stdint.h>

#define K_DIM 4096
#define N_DIM 16384
#define M_MAX 8192

#define BM 128
#define BN 128
#define BK 64                        // bf16 elems of K per stage (128 bytes)
#define STAGES 3
#define KSTEPS (K_DIM / BK)          // 64
#define A_SMEM (BM * 128)            // 16384 bytes
#define B_SMEM (BN * 128)            // 16384 bytes
#define STAGE_BYTES (A_SMEM + B_SMEM)    // 32768
#define GEMM_SMEM (STAGES * STAGE_BYTES) // 98304 per CTA (2 CTAs/SM = 192KB)
#define GTHREADS 128

#define TILES_M (M_MAX / BM)         // 64
#define TILES_N (N_DIM / BN)         // 128
#define RASTER_GROUP 8               // n-tiles per raster column group

// ------------------------- scratch (device globals; no runtime alloc) ---
__device__ __nv_bfloat16 g_xq[(size_t)M_MAX * K_DIM];   // 64 MB bf16 x
__device__ __nv_bfloat16 g_wq[(size_t)N_DIM * K_DIM];   // 128 MB bf16 w
__device__ float g_sx[M_MAX];

// ------------------------- helpers --------------------------------------
__device__ __forceinline__ uint32_t smem_u32(const void* p) {
    uint32_t a;
    asm("{ .reg .u64 t; cvta.to.shared.u64 t, %1; cvt.u32.u64 %0, t; }"
        : "=r"(a) : "l"(p));
    return a;
}
__device__ __forceinline__ uint32_t swz128(uint32_t b) { return b ^ ((b >> 3) & 0x70); }

__device__ __forceinline__ void cp_async16(uint32_t s, const void* g) {
    asm volatile("cp.async.cg.shared.global [%0], [%1], 16;" :: "r"(s), "l"(g));
}
__device__ __forceinline__ void cp_commit() {
    asm volatile("cp.async.commit_group;" ::: "memory");
}
__device__ __forceinline__ void cp_wait1() {
    asm volatile("cp.async.wait_group 1;" ::: "memory");
}

__device__ __forceinline__ void ldm_x4(uint32_t* r, uint32_t addr) {
    asm volatile("ldmatrix.sync.aligned.m8n8.x4.shared.b16 {%0,%1,%2,%3}, [%4];"
        : "=r"(r[0]), "=r"(r[1]), "=r"(r[2]), "=r"(r[3]) : "r"(addr));
}

// bf16 HMMA: D(f32) += A(bf16) * B(bf16), m16n8k16
__device__ __forceinline__ void mma_bf16(float* c, const uint32_t* a, uint32_t b0, uint32_t b1) {
    asm volatile("mma.sync.aligned.m16n8k16.row.col.f32.bf16.bf16.f32 "
        "{%0,%1,%2,%3}, {%4,%5,%6,%7}, {%8,%9}, {%0,%1,%2,%3};"
        : "+f"(c[0]), "+f"(c[1]), "+f"(c[2]), "+f"(c[3])
        : "r"(a[0]), "r"(a[1]), "r"(a[2]), "r"(a[3]), "r"(b0), "r"(b1));
}

__device__ __forceinline__ uint32_t pack_bf16x2(float a, float b) {
    __nv_bfloat162 h = __floats2bfloat162_rn(a, b);
    return *reinterpret_cast<uint32_t*>(&h);
}

// ------------------------- kernel 1: quantize x -> bf16 ------------------
__global__ void __launch_bounds__(256) quant_x_kernel(const float* __restrict__ x) {
    const int row = blockIdx.x;
    const float4* xv = reinterpret_cast<const float4*>(x + (size_t)row * K_DIM);

    float4 v[4];
    float m = 0.f;
#pragma unroll
    for (int i = 0; i < 4; i++) {
        v[i] = xv[threadIdx.x * 4 + i];
        m = fmaxf(m, fmaxf(fmaxf(fabsf(v[i].x), fabsf(v[i].y)),
                           fmaxf(fabsf(v[i].z), fabsf(v[i].w))));
    }
#pragma unroll
    for (int o = 16; o; o >>= 1) m = fmaxf(m, __shfl_xor_sync(0xFFFFFFFFu, m, o));

    __shared__ float sm[8];
    if ((threadIdx.x & 31) == 0) sm[threadIdx.x >> 5] = m;
    __syncthreads();
    if (threadIdx.x < 32) {
        float t = (threadIdx.x < 8) ? sm[threadIdx.x] : 0.f;
#pragma unroll
        for (int o = 4; o; o >>= 1) t = fmaxf(t, __shfl_xor_sync(0xFFFFFFFFu, t, o));
        if (threadIdx.x == 0) sm[0] = t;
    }
    __syncthreads();
    float sx = sm[0] / 127.0f;
    if (sx == 0.f) sx = 1.0f;
    if (threadIdx.x == 0) g_sx[row] = sx;

    uint4 o1, o2;
    float q[16];
#pragma unroll
    for (int i = 0; i < 4; i++) {
        q[4 * i + 0] = fminf(fmaxf(rintf(v[i].x / sx), -127.f), 127.f);
        q[4 * i + 1] = fminf(fmaxf(rintf(v[i].y / sx), -127.f), 127.f);
        q[4 * i + 2] = fminf(fmaxf(rintf(v[i].z / sx), -127.f), 127.f);
        q[4 * i + 3] = fminf(fmaxf(rintf(v[i].w / sx), -127.f), 127.f);
    }
    o1.x = pack_bf16x2(q[0], q[1]);  o1.y = pack_bf16x2(q[2], q[3]);
    o1.z = pack_bf16x2(q[4], q[5]);  o1.w = pack_bf16x2(q[6], q[7]);
    o2.x = pack_bf16x2(q[8], q[9]);  o2.y = pack_bf16x2(q[10], q[11]);
    o2.z = pack_bf16x2(q[12], q[13]); o2.w = pack_bf16x2(q[14], q[15]);
    uint4* outp = reinterpret_cast<uint4*>(g_xq + (size_t)row * K_DIM);
    outp[threadIdx.x * 2 + 0] = o1;
    outp[threadIdx.x * 2 + 1] = o2;
}

// ------------------------- kernel 2: weights int32 -> bf16 ---------------
__global__ void __launch_bounds__(256) quant_w_kernel(const int* __restrict__ w) {
    const long total8 = (long)N_DIM * K_DIM / 8;
    long gid = blockIdx.x * 256L + threadIdx.x;
    long stride = gridDim.x * 256L;
    const int4* wv = reinterpret_cast<const int4*>(w);
    uint4* out = reinterpret_cast<uint4*>(g_wq);
    for (; gid < total8; gid += stride) {
        int4 a = wv[gid * 2 + 0];
        int4 b = wv[gid * 2 + 1];
        uint4 o;
        o.x = pack_bf16x2((float)a.x, (float)a.y);
        o.y = pack_bf16x2((float)a.z, (float)a.w);
        o.z = pack_bf16x2((float)b.x, (float)b.y);
        o.w = pack_bf16x2((float)b.z, (float)b.w);
        out[gid] = o;
    }
}

// ------------------------- kernel 3: bf16 HMMA GEMM ----------------------
// 128x128 CTA tile, 4 warps (2 M x 2 N), 64x64 warp tiles, 2 CTAs/SM,
// 3-stage cp.async pipeline (wait_group 1), fragment double-buffering.
__global__ void __launch_bounds__(GTHREADS, 2) gemm_kernel(float* __restrict__ out,
                                                           const float* __restrict__ scale,
                                                           const float* __restrict__ bias) {
    extern __shared__ char smem[];
    const uint32_t sb = smem_u32(smem);
    const int tid = threadIdx.x;
    const int wid = tid >> 5;           // 0..3
    const int lane = tid & 31;

    // ---- L2-friendly rasterization ---------------------------------------
    const int bid = blockIdx.x;
    const int group = bid / (RASTER_GROUP * TILES_M);
    const int rem = bid % (RASTER_GROUP * TILES_M);
    const int mt = rem / RASTER_GROUP;
    const int nt = group * RASTER_GROUP + (rem % RASTER_GROUP);
    const int n0 = nt * BN;
    const int m0 = mt * BM;

    const int wm = wid >> 1;            // 0..1
    const int wn = wid & 1;             // 0..1

    // --- cp.async addressing ----------------------------------------------
    const int r0 = tid >> 3;            // 0..15
    const int c0 = tid & 7;             // 0..7 (16B chunk in row)
    const char* baseA = reinterpret_cast<const char*>(g_xq)
                        + (size_t)(m0 + r0) * (K_DIM * 2) + c0 * 16;
    const char* baseB = reinterpret_cast<const char*>(g_wq)
                        + (size_t)(n0 + r0) * (K_DIM * 2) + c0 * 16;
    const uint32_t sA0 = sb + swz128((uint32_t)(r0 * 128 + c0 * 16));
    const uint32_t sB0 = sA0 + A_SMEM;  // +16384: swizzle-safe offset

    // --- ldmatrix per-lane addressing -------------------------------------
    const int q = lane >> 3;
    const int rw = lane & 7;
    const uint32_t mask = (uint32_t)rw << 4;
    const int kbA = (q >> 1) * 16;
    const int kbB = (q & 1) * 16;
    uint32_t rowA[4], rowB[4];
#pragma unroll
    for (int mi = 0; mi < 4; mi++)
        rowA[mi] = (uint32_t)((wm * 64 + mi * 16 + (q & 1) * 8 + rw) * 128);
#pragma unroll
    for (int nj = 0; nj < 4; nj++)
        rowB[nj] = (uint32_t)(A_SMEM + (wn * 64 + nj * 16 + (q >> 1) * 8 + rw) * 128);

    float acc[4][8][4];
#pragma unroll
    for (int mi = 0; mi < 4; mi++)
#pragma unroll
        for (int nj = 0; nj < 8; nj++)
#pragma unroll
            for (int t = 0; t < 4; t++) acc[mi][nj][t] = 0.f;

    // --- stage loader: 8 A-chunks + 8 B-chunks of 16B per thread ----------
    auto load_stage = [&](int slot, int kblk) {
        const uint32_t soff = (uint32_t)slot * STAGE_BYTES;
        const int kb = kblk * 128;
#pragma unroll
        for (int i = 0; i < 8; i++)     // A: 128 rows, 16 rows per step
            cp_async16(sA0 + soff + i * 2048u, baseA + (size_t)i * 131072 + kb);
#pragma unroll
        for (int i = 0; i < 8; i++)     // B: 128 rows
            cp_async16(sB0 + soff + i * 2048u, baseB + (size_t)i * 131072 + kb);
    };

    // --- fragment loader ----------------------------------------------------
    auto load_frags = [&](uint32_t a[4][4], uint32_t b[4][4], uint32_t stg, int ks) {
        const uint32_t koffA = (uint32_t)((ks * 32 + kbA) ^ (int)mask);
        const uint32_t koffB = (uint32_t)((ks * 32 + kbB) ^ (int)mask);
#pragma unroll
        for (int mi = 0; mi < 4; mi++) ldm_x4(a[mi], stg + rowA[mi] + koffA);
#pragma unroll
        for (int nj = 0; nj < 4; nj++) ldm_x4(b[nj], stg + rowB[nj] + koffB);
    };

    // prologue: stages 0,1 in flight
    load_stage(0, 0); cp_commit();
    load_stage(1, 1); cp_commit();

    uint32_t af[2][4][4], bf[2][4][4];

    for (int k = 0; k < KSTEPS; k++) {
        cp_wait1();                      // stage k complete (1 pending allowed)
        __syncthreads();                 // stage k-1 fully consumed by all warps
        if (k + 2 < KSTEPS)
            load_stage((k + 2) % STAGES, k + 2);   // slot consumed at iter k-1
        cp_commit();                     // unconditional: group accounting

        const uint32_t stg = sb + (uint32_t)(k % STAGES) * STAGE_BYTES;
        load_frags(af[0], bf[0], stg, 0);

#pragma unroll
        for (int ks = 0; ks < 4; ks++) {
            const int pb = ks & 1;
            if (ks < 3) load_frags(af[pb ^ 1], bf[pb ^ 1], stg, ks + 1);
#pragma unroll
            for (int mi = 0; mi < 4; mi++) {
#pragma unroll
                for (int nj = 0; nj < 4; nj++) {
                    mma_bf16(acc[mi][2 * nj + 0], af[pb][mi], bf[pb][nj][0], bf[pb][nj][1]);
                    mma_bf16(acc[mi][2 * nj + 1], af[pb][mi], bf[pb][nj][2], bf[pb][nj][3]);
                }
            }
        }
    }

    // ------------- epilogue: dequant + bias, float2 stores ---------------
    const int nbase = n0 + wn * 64;
#pragma unroll
    for (int mi = 0; mi < 4; mi++) {
        const int mlo = m0 + wm * 64 + mi * 16 + (lane >> 2);
        const int mhi = mlo + 8;
        const float slo = g_sx[mlo];
        const float shi = g_sx[mhi];
        float* orow_lo = out + (size_t)mlo * N_DIM + nbase;
        float* orow_hi = out + (size_t)mhi * N_DIM + nbase;
#pragma unroll
        for (int nj = 0; nj < 8; nj++) {
            const int n = nj * 8 + 2 * (lane & 3);
            const float2 sc = *reinterpret_cast<const float2*>(scale + nbase + n);
            const float2 bi = *reinterpret_cast<const float2*>(bias + nbase + n);
            const float* c = acc[mi][nj];
            float2 vlo, vhi;
            vlo.x = fmaf(c[0] * slo, sc.x, bi.x);
            vlo.y = fmaf(c[1] * slo, sc.y, bi.y);
            vhi.x = fmaf(c[2] * shi, sc.x, bi.x);
            vhi.y = fmaf(c[3] * shi, sc.y, bi.y);
            *reinterpret_cast<float2*>(orow_lo + n) = vlo;
            *reinterpret_cast<float2*>(orow_hi + n) = vhi;
        }
    }
}

// ------------------------- launch ---------------------------------------
extern "C" void kernel_launch(void* const* d_in, const int* in_sizes, int n_in,
                              void* d_out, int out_size) {
    const float* x = (const float*)d_in[0];
    const int* w = (const int*)d_in[1];
    const float* scale = (const float*)d_in[2];
    const float* bias = (const float*)d_in[3];
    float* out = (float*)d_out;

    const int M = in_sizes[0] / K_DIM;   // 8192

    static int smem_set = 0;
    if (!smem_set) {
        cudaFuncSetAttribute(gemm_kernel, cudaFuncAttributeMaxDynamicSharedMemorySize,
                             GEMM_SMEM);
        smem_set = 1;
    }

    quant_x_kernel<<<M, 256>>>(x);
    quant_w_kernel<<<16384, 256>>>(w);
    gemm_kernel<<<TILES_M * TILES_N, GTHREADS, GEMM_SMEM>>>(out, scale, bias);
}

// round 9
// speedup vs baseline: 3.5066x; 1.0973x over previous
#include <cuda_runtime.h>
#include <cuda_bf16.h>
#include <stdint.h>

#define K_DIM 4096
#define N_DIM 16384
#define M_MAX 8192

#define BM 128
#define BN 128
#define BK 64                        // bf16 elems of K per stage (128 bytes)
#define STAGES 3
#define KSTEPS (K_DIM / BK)          // 64
#define A_SMEM (BM * 128)            // 16384 bytes
#define B_SMEM (BN * 128)            // 16384 bytes
#define STAGE_BYTES (A_SMEM + B_SMEM)    // 32768
#define GEMM_SMEM (STAGES * STAGE_BYTES) // 98304 per CTA (2 CTAs/SM = 192KB)
#define GTHREADS 128

#define TILES_M (M_MAX / BM)         // 64
#define TILES_N (N_DIM / BN)         // 128
#define RASTER_GROUP 8               // n-tiles per raster column group

// ------------------------- scratch (device globals; no runtime alloc) ---
__device__ __nv_bfloat16 g_xq[(size_t)M_MAX * K_DIM];   // 64 MB bf16 x
__device__ __nv_bfloat16 g_wq[(size_t)N_DIM * K_DIM];   // 128 MB bf16 w
__device__ float g_sx[M_MAX];

// ------------------------- helpers --------------------------------------
__device__ __forceinline__ uint32_t smem_u32(const void* p) {
    uint32_t a;
    asm("{ .reg .u64 t; cvta.to.shared.u64 t, %1; cvt.u32.u64 %0, t; }"
        : "=r"(a) : "l"(p));
    return a;
}
__device__ __forceinline__ uint32_t swz128(uint32_t b) { return b ^ ((b >> 3) & 0x70); }

__device__ __forceinline__ void cp_async16(uint32_t s, const void* g) {
    asm volatile("cp.async.cg.shared.global [%0], [%1], 16;" :: "r"(s), "l"(g));
}
__device__ __forceinline__ void cp_commit() {
    asm volatile("cp.async.commit_group;" ::: "memory");
}
__device__ __forceinline__ void cp_wait1() {
    asm volatile("cp.async.wait_group 1;" ::: "memory");
}

__device__ __forceinline__ void ldm_x4(uint32_t* r, uint32_t addr) {
    asm volatile("ldmatrix.sync.aligned.m8n8.x4.shared.b16 {%0,%1,%2,%3}, [%4];"
        : "=r"(r[0]), "=r"(r[1]), "=r"(r[2]), "=r"(r[3]) : "r"(addr));
}

// bf16 HMMA: D(f32) += A(bf16) * B(bf16), m16n8k16
__device__ __forceinline__ void mma_bf16(float* c, const uint32_t* a, uint32_t b0, uint32_t b1) {
    asm volatile("mma.sync.aligned.m16n8k16.row.col.f32.bf16.bf16.f32 "
        "{%0,%1,%2,%3}, {%4,%5,%6,%7}, {%8,%9}, {%0,%1,%2,%3};"
        : "+f"(c[0]), "+f"(c[1]), "+f"(c[2]), "+f"(c[3])
        : "r"(a[0]), "r"(a[1]), "r"(a[2]), "r"(a[3]), "r"(b0), "r"(b1));
}

__device__ __forceinline__ uint32_t pack_bf16x2(float a, float b) {
    __nv_bfloat162 h = __floats2bfloat162_rn(a, b);
    return *reinterpret_cast<uint32_t*>(&h);
}

// ------------------------- kernel 1: quantize x -> bf16 ------------------
__global__ void __launch_bounds__(256) quant_x_kernel(const float* __restrict__ x) {
    const int row = blockIdx.x;
    const float4* xv = reinterpret_cast<const float4*>(x + (size_t)row * K_DIM);

    float4 v[4];
    float m = 0.f;
#pragma unroll
    for (int i = 0; i < 4; i++) {
        v[i] = xv[threadIdx.x * 4 + i];
        m = fmaxf(m, fmaxf(fmaxf(fabsf(v[i].x), fabsf(v[i].y)),
                           fmaxf(fabsf(v[i].z), fabsf(v[i].w))));
    }
#pragma unroll
    for (int o = 16; o; o >>= 1) m = fmaxf(m, __shfl_xor_sync(0xFFFFFFFFu, m, o));

    __shared__ float sm[8];
    if ((threadIdx.x & 31) == 0) sm[threadIdx.x >> 5] = m;
    __syncthreads();
    if (threadIdx.x < 32) {
        float t = (threadIdx.x < 8) ? sm[threadIdx.x] : 0.f;
#pragma unroll
        for (int o = 4; o; o >>= 1) t = fmaxf(t, __shfl_xor_sync(0xFFFFFFFFu, t, o));
        if (threadIdx.x == 0) sm[0] = t;
    }
    __syncthreads();
    float sx = sm[0] / 127.0f;
    if (sx == 0.f) sx = 1.0f;
    if (threadIdx.x == 0) g_sx[row] = sx;

    uint4 o1, o2;
    float q[16];
#pragma unroll
    for (int i = 0; i < 4; i++) {
        q[4 * i + 0] = fminf(fmaxf(rintf(v[i].x / sx), -127.f), 127.f);
        q[4 * i + 1] = fminf(fmaxf(rintf(v[i].y / sx), -127.f), 127.f);
        q[4 * i + 2] = fminf(fmaxf(rintf(v[i].z / sx), -127.f), 127.f);
        q[4 * i + 3] = fminf(fmaxf(rintf(v[i].w / sx), -127.f), 127.f);
    }
    o1.x = pack_bf16x2(q[0], q[1]);  o1.y = pack_bf16x2(q[2], q[3]);
    o1.z = pack_bf16x2(q[4], q[5]);  o1.w = pack_bf16x2(q[6], q[7]);
    o2.x = pack_bf16x2(q[8], q[9]);  o2.y = pack_bf16x2(q[10], q[11]);
    o2.z = pack_bf16x2(q[12], q[13]); o2.w = pack_bf16x2(q[14], q[15]);
    uint4* outp = reinterpret_cast<uint4*>(g_xq + (size_t)row * K_DIM);
    outp[threadIdx.x * 2 + 0] = o1;
    outp[threadIdx.x * 2 + 1] = o2;
}

// ------------------------- kernel 2: weights int32 -> bf16 ---------------
__global__ void __launch_bounds__(256) quant_w_kernel(const int* __restrict__ w) {
    const long total8 = (long)N_DIM * K_DIM / 8;
    long gid = blockIdx.x * 256L + threadIdx.x;
    long stride = gridDim.x * 256L;
    const int4* wv = reinterpret_cast<const int4*>(w);
    uint4* out = reinterpret_cast<uint4*>(g_wq);
    for (; gid < total8; gid += stride) {
        int4 a = wv[gid * 2 + 0];
        int4 b = wv[gid * 2 + 1];
        uint4 o;
        o.x = pack_bf16x2((float)a.x, (float)a.y);
        o.y = pack_bf16x2((float)a.z, (float)a.w);
        o.z = pack_bf16x2((float)b.x, (float)b.y);
        o.w = pack_bf16x2((float)b.z, (float)b.w);
        out[gid] = o;
    }
}

// ------------------------- kernel 3: bf16 HMMA GEMM ----------------------
// 128x128 CTA tile, 4 warps (2 M x 2 N), 64x64 warp tiles, 2 CTAs/SM,
// 3-stage cp.async pipeline; commit-then-wait ordering guarantees stages
// k AND k+1 complete -> cross-stage fragment double-buffering.
__global__ void __launch_bounds__(GTHREADS, 2) gemm_kernel(float* __restrict__ out,
                                                           const float* __restrict__ scale,
                                                           const float* __restrict__ bias) {
    extern __shared__ char smem[];
    const uint32_t sb = smem_u32(smem);
    const int tid = threadIdx.x;
    const int wid = tid >> 5;           // 0..3
    const int lane = tid & 31;

    // ---- L2-friendly rasterization ---------------------------------------
    const int bid = blockIdx.x;
    const int group = bid / (RASTER_GROUP * TILES_M);
    const int rem = bid % (RASTER_GROUP * TILES_M);
    const int mt = rem / RASTER_GROUP;
    const int nt = group * RASTER_GROUP + (rem % RASTER_GROUP);
    const int n0 = nt * BN;
    const int m0 = mt * BM;

    const int wm = wid >> 1;            // 0..1
    const int wn = wid & 1;             // 0..1

    // --- cp.async addressing ----------------------------------------------
    const int r0 = tid >> 3;            // 0..15
    const int c0 = tid & 7;             // 0..7 (16B chunk in row)
    const char* baseA = reinterpret_cast<const char*>(g_xq)
                        + (size_t)(m0 + r0) * (K_DIM * 2) + c0 * 16;
    const char* baseB = reinterpret_cast<const char*>(g_wq)
                        + (size_t)(n0 + r0) * (K_DIM * 2) + c0 * 16;
    const uint32_t sA0 = sb + swz128((uint32_t)(r0 * 128 + c0 * 16));
    const uint32_t sB0 = sA0 + A_SMEM;  // +16384: swizzle-safe offset

    // --- ldmatrix per-lane addressing -------------------------------------
    const int q = lane >> 3;
    const int rw = lane & 7;
    const uint32_t mask = (uint32_t)rw << 4;
    const int kbA = (q >> 1) * 16;
    const int kbB = (q & 1) * 16;
    uint32_t rowA[4], rowB[4];
#pragma unroll
    for (int mi = 0; mi < 4; mi++)
        rowA[mi] = (uint32_t)((wm * 64 + mi * 16 + (q & 1) * 8 + rw) * 128);
#pragma unroll
    for (int nj = 0; nj < 4; nj++)
        rowB[nj] = (uint32_t)(A_SMEM + (wn * 64 + nj * 16 + (q >> 1) * 8 + rw) * 128);

    float acc[4][8][4];
#pragma unroll
    for (int mi = 0; mi < 4; mi++)
#pragma unroll
        for (int nj = 0; nj < 8; nj++)
#pragma unroll
            for (int t = 0; t < 4; t++) acc[mi][nj][t] = 0.f;

    // --- stage loader: 8 A-chunks + 8 B-chunks of 16B per thread ----------
    auto load_stage = [&](int slot, int kblk) {
        const uint32_t soff = (uint32_t)slot * STAGE_BYTES;
        const int kb = kblk * 128;
#pragma unroll
        for (int i = 0; i < 8; i++)     // A: 128 rows, 16 rows per step
            cp_async16(sA0 + soff + i * 2048u, baseA + (size_t)i * 131072 + kb);
#pragma unroll
        for (int i = 0; i < 8; i++)     // B: 128 rows
            cp_async16(sB0 + soff + i * 2048u, baseB + (size_t)i * 131072 + kb);
    };

    // --- fragment loader ----------------------------------------------------
    auto load_frags = [&](uint32_t a[4][4], uint32_t b[4][4], uint32_t stg, int ks) {
        const uint32_t koffA = (uint32_t)((ks * 32 + kbA) ^ (int)mask);
        const uint32_t koffB = (uint32_t)((ks * 32 + kbB) ^ (int)mask);
#pragma unroll
        for (int mi = 0; mi < 4; mi++) ldm_x4(a[mi], stg + rowA[mi] + koffA);
#pragma unroll
        for (int nj = 0; nj < 4; nj++) ldm_x4(b[nj], stg + rowB[nj] + koffB);
    };

    // prologue: stages 0,1 in flight; preload frags for stage 0 ks=0
    load_stage(0, 0); cp_commit();
    load_stage(1, 1); cp_commit();

    uint32_t af[2][4][4], bf[2][4][4];

    cp_wait1();                          // stage 0 complete
    __syncthreads();
    load_frags(af[0], bf[0], sb, 0);     // stage 0, ks=0

    for (int k = 0; k < KSTEPS; k++) {
        __syncthreads();                 // all warps done reading slot (k-1)%3
        if (k + 2 < KSTEPS)
            load_stage((k + 2) % STAGES, k + 2);
        cp_commit();                     // newest group = stage k+2
        cp_wait1();                      // stages k AND k+1 complete

        const uint32_t stg  = sb + (uint32_t)(k % STAGES) * STAGE_BYTES;
        const uint32_t stgn = sb + (uint32_t)((k + 1) % STAGES) * STAGE_BYTES;

#pragma unroll
        for (int ks = 0; ks < 4; ks++) {
            const int pb = ks & 1;
            const int nb = pb ^ 1;
            // prefetch next fragments (next ks, or next stage's ks=0)
            if (ks < 3) load_frags(af[nb], bf[nb], stg, ks + 1);
            else        load_frags(af[nb], bf[nb], stgn, 0);
#pragma unroll
            for (int mi = 0; mi < 4; mi++) {
#pragma unroll
                for (int nj = 0; nj < 4; nj++) {
                    mma_bf16(acc[mi][2 * nj + 0], af[pb][mi], bf[pb][nj][0], bf[pb][nj][1]);
                    mma_bf16(acc[mi][2 * nj + 1], af[pb][mi], bf[pb][nj][2], bf[pb][nj][3]);
                }
            }
        }
    }

    // ------------- epilogue: dequant + bias, float2 stores ---------------
    const int nbase = n0 + wn * 64;
#pragma unroll
    for (int mi = 0; mi < 4; mi++) {
        const int mlo = m0 + wm * 64 + mi * 16 + (lane >> 2);
        const int mhi = mlo + 8;
        const float slo = g_sx[mlo];
        const float shi = g_sx[mhi];
        float* orow_lo = out + (size_t)mlo * N_DIM + nbase;
        float* orow_hi = out + (size_t)mhi * N_DIM + nbase;
#pragma unroll
        for (int nj = 0; nj < 8; nj++) {
            const int n = nj * 8 + 2 * (lane & 3);
            const float2 sc = *reinterpret_cast<const float2*>(scale + nbase + n);
            const float2 bi = *reinterpret_cast<const float2*>(bias + nbase + n);
            const float* c = acc[mi][nj];
            float2 vlo, vhi;
            vlo.x = fmaf(c[0] * slo, sc.x, bi.x);
            vlo.y = fmaf(c[1] * slo, sc.y, bi.y);
            vhi.x = fmaf(c[2] * shi, sc.x, bi.x);
            vhi.y = fmaf(c[3] * shi, sc.y, bi.y);
            *reinterpret_cast<float2*>(orow_lo + n) = vlo;
            *reinterpret_cast<float2*>(orow_hi + n) = vhi;
        }
    }
}

// ------------------------- launch ---------------------------------------
extern "C" void kernel_launch(void* const* d_in, const int* in_sizes, int n_in,
                              void* d_out, int out_size) {
    const float* x = (const float*)d_in[0];
    const int* w = (const int*)d_in[1];
    const float* scale = (const float*)d_in[2];
    const float* bias = (const float*)d_in[3];
    float* out = (float*)d_out;

    const int M = in_sizes[0] / K_DIM;   // 8192

    static int smem_set = 0;
    if (!smem_set) {
        cudaFuncSetAttribute(gemm_kernel, cudaFuncAttributeMaxDynamicSharedMemorySize,
                             GEMM_SMEM);
        smem_set = 1;
    }

    quant_x_kernel<<<M, 256>>>(x);
    quant_w_kernel<<<16384, 256>>>(w);
    gemm_kernel<<<TILES_M * TILES_N, GTHREADS, GEMM_SMEM>>>(out, scale, bias);
}